// round 7
// baseline (speedup 1.0000x reference)
#include <cuda_runtime.h>
#include <cuda_bf16.h>
#include <float.h>
#include <math.h>
#include <cstdint>

// Problem constants
constexpr int Bc = 1024;
constexpr int Sc = 200;
constexpr int Dc = 128;
constexpr int Hc = 128;
constexpr int Nc = 64;
constexpr int ROWS = Bc * Sc;             // 204800
constexpr int TILES = ROWS / 128;         // 1600
constexpr int OUT_CONCAT = Bc * (Dc + 1); // 132096

// Scratch
__device__ float g_P[Sc * Hc];
__device__ float g_scores[ROWS];
__device__ float g_posloss[Bc];
__device__ float g_negsum[Bc];
__device__ int   g_flags = 0;   // bit0 = bad (uint8), bit1 = f32
__device__ int   g_done  = 0;   // k2 completion counter

__device__ __forceinline__ uint32_t smem_u32(const void* p) {
    uint32_t a;
    asm("{ .reg .u64 t; cvta.to.shared.u64 t, %1; cvt.u32.u64 %0, t; }" : "=r"(a) : "l"(p));
    return a;
}

#define LDMX4(r0, r1, r2, r3, addr) \
    asm volatile("ldmatrix.sync.aligned.m8n8.x4.shared.b16 {%0,%1,%2,%3}, [%4];" \
        : "=r"(r0), "=r"(r1), "=r"(r2), "=r"(r3) : "r"(addr))
#define LDMX2(r0, r1, addr) \
    asm volatile("ldmatrix.sync.aligned.m8n8.x2.shared.b16 {%0,%1}, [%2];" \
        : "=r"(r0), "=r"(r1) : "r"(addr))
#define MMA16816(c, a, b) \
    asm volatile("mma.sync.aligned.m16n8k16.row.col.f32.bf16.bf16.f32 " \
        "{%0,%1,%2,%3},{%4,%5,%6,%7},{%8,%9},{%0,%1,%2,%3};" \
        : "+f"((c)[0]), "+f"((c)[1]), "+f"((c)[2]), "+f"((c)[3]) \
        : "r"((a)[0]), "r"((a)[1]), "r"((a)[2]), "r"((a)[3]), "r"((b)[0]), "r"((b)[1]))

__device__ __forceinline__ uint32_t swz(int row, int chunk) {
    return (uint32_t)(row * 256 + ((chunk ^ (row & 7)) << 4));
}

__device__ __forceinline__ float softplus_f(float x) {
    return fmaxf(x, 0.f) + log1pf(expf(-fabsf(x)));
}
__device__ __forceinline__ float tanh_fast(float x) {
    float t;
    asm("tanh.approx.f32 %0, %1;" : "=f"(t) : "f"(x));
    return t;
}
__device__ __forceinline__ int mask_at(const void* m, int idx, int mode) {
    if (mode == 2) return ((const unsigned char*)m)[idx] != 0;
    if (mode == 1) return ((const float*)m)[idx] != 0.f;
    return ((const int*)m)[idx] != 0;
}

// ===================== P rows + fused mask-dtype detection =====================
__global__ void k0_P(const float* __restrict__ pos, const float* __restrict__ Wp,
                     const uint4* __restrict__ mraw) {
    const int s = blockIdx.x, h = threadIdx.x;
    const int i = s * 128 + h;
    if (i < (Bc * Sc) / 16) {
        uint4 v = mraw[i];
        int fl = 0;
        uint32_t ws[4] = {v.x, v.y, v.z, v.w};
#pragma unroll
        for (int j = 0; j < 4; j++) {
            if (ws[j] == 0x3F800000u) fl |= 2;
            else if (ws[j] > 1u) fl |= 1;
        }
        if (fl) atomicOr(&g_flags, fl);
    }
    float acc = 0.f;
#pragma unroll 8
    for (int d = 0; d < Dc; d++)
        acc = fmaf(__ldg(&pos[s * Dc + d]), __ldg(&Wp[d * Hc + h]), acc);
    g_P[s * Hc + h] = acc;
}

// ===================== mma.sync score kernel =====================
constexpr int OFF_AHI = 0;
constexpr int OFF_ALO = 32768;
constexpr int OFF_RED = 65536;                  // 128*9*4 = 4608
constexpr int SMEM_K1 = OFF_RED + 128 * 9 * 4;  // 70144

__device__ __forceinline__ void split4(float4 v, uint2& hh, uint2& ll) {
    uint32_t ux = __float_as_uint(v.x), uy = __float_as_uint(v.y);
    uint32_t uz = __float_as_uint(v.z), uw = __float_as_uint(v.w);
    hh.x = __byte_perm(ux, uy, 0x7632);
    hh.y = __byte_perm(uz, uw, 0x7632);
    float lx = v.x - __uint_as_float(ux & 0xFFFF0000u);
    float ly = v.y - __uint_as_float(uy & 0xFFFF0000u);
    float lz = v.z - __uint_as_float(uz & 0xFFFF0000u);
    float lw = v.w - __uint_as_float(uw & 0xFFFF0000u);
    asm("cvt.rn.bf16x2.f32 %0, %1, %2;" : "=r"(ll.x) : "f"(ly), "f"(lx));
    asm("cvt.rn.bf16x2.f32 %0, %1, %2;" : "=r"(ll.y) : "f"(lw), "f"(lz));
}

__global__ void __launch_bounds__(256, 2)
k1_mma(const float* __restrict__ X, const float* __restrict__ We, const float* __restrict__ z) {
    extern __shared__ char smc[];
    const uint32_t smb = smem_u32(smc);
    float* red = (float*)(smc + OFF_RED);
    const int tid = threadIdx.x;
    const int wid = tid >> 5, l = tid & 31;
    const int bn = wid * 16;

    // ---- stage WeT hi/lo, load B fragments ----
    for (int i = tid; i < Dc * Hc; i += 256) {
        int d = i >> 7, h = i & 127;
        float v = We[i];
        __nv_bfloat16 hi = __float2bfloat16(v);
        __nv_bfloat16 lo = __float2bfloat16(v - __bfloat162float(hi));
        uint32_t a = swz(h, d >> 3) + (uint32_t)((d & 7) * 2);
        *(__nv_bfloat16*)(smc + OFF_AHI + a) = hi;
        *(__nv_bfloat16*)(smc + OFF_ALO + a) = lo;
    }
    __syncthreads();

    uint32_t Bh[8][2][2], Bl[8][2][2];
    {
        const int brow = bn + (l & 7);
        const int bc = (l >> 3) & 1;
#pragma unroll
        for (int ks = 0; ks < 8; ks++) {
#pragma unroll
            for (int j = 0; j < 2; j++) {
                uint32_t a = swz(brow + j * 8, 2 * ks + bc);
                LDMX2(Bh[ks][j][0], Bh[ks][j][1], smb + OFF_AHI + a);
                LDMX2(Bl[ks][j][0], Bl[ks][j][1], smb + OFF_ALO + a);
            }
        }
    }
    const int c0 = bn + (l & 3) * 2;
    const float zv0 = __ldg(&z[c0]),     zv1 = __ldg(&z[c0 + 1]);
    const float zv2 = __ldg(&z[c0 + 8]), zv3 = __ldg(&z[c0 + 9]);
    __syncthreads();

    const int arow_off = (l & 7) + ((l >> 3) & 1) * 8;
    const int achk_off = (l >> 4) & 1;

    const int GD = gridDim.x;
    int t = blockIdx.x;
    float4 pf[16];
    if (t < TILES) {
        const float4* Xg = (const float4*)(X + (size_t)t * (128 * 128));
#pragma unroll
        for (int jj = 0; jj < 16; jj++) pf[jj] = Xg[tid + jj * 256];
    }

    for (; t < TILES; t += GD) {
        // ---- convert + store prefetched tile ----
#pragma unroll
        for (int jj = 0; jj < 16; jj++) {
            int i4 = tid + jj * 256;
            int elem = i4 * 4;
            int row = elem >> 7, col = elem & 127;
            uint32_t a = swz(row, col >> 3) + (uint32_t)((col & 7) * 2);
            uint2 hh, ll;
            split4(pf[jj], hh, ll);
            *(uint2*)(smc + OFF_AHI + a) = hh;
            *(uint2*)(smc + OFF_ALO + a) = ll;
        }
        __syncthreads();

        // ---- prefetch next tile (hidden behind GEMM) ----
        const int tn = t + GD;
        if (tn < TILES) {
            const float4* Xg = (const float4*)(X + (size_t)tn * (128 * 128));
#pragma unroll
            for (int jj = 0; jj < 16; jj++) pf[jj] = Xg[tid + jj * 256];
        }

        // ---- GEMM: C = Xhi*Whi + Xhi*Wlo + Xlo*Whi ----
        float C[8][2][4];
#pragma unroll
        for (int f = 0; f < 8; f++)
#pragma unroll
            for (int j = 0; j < 2; j++)
#pragma unroll
                for (int q = 0; q < 4; q++) C[f][j][q] = 0.f;

#pragma unroll
        for (int ks = 0; ks < 8; ks++) {
            uint32_t A[8][4];
#pragma unroll
            for (int f = 0; f < 8; f++) {
                uint32_t a = swz(f * 16 + arow_off, 2 * ks + achk_off);
                LDMX4(A[f][0], A[f][1], A[f][2], A[f][3], smb + OFF_AHI + a);
            }
#pragma unroll
            for (int f = 0; f < 8; f++) {
                MMA16816(C[f][0], A[f], Bh[ks][0]);
                MMA16816(C[f][1], A[f], Bh[ks][1]);
                MMA16816(C[f][0], A[f], Bl[ks][0]);
                MMA16816(C[f][1], A[f], Bl[ks][1]);
            }
#pragma unroll
            for (int f = 0; f < 8; f++) {
                uint32_t a = swz(f * 16 + arow_off, 2 * ks + achk_off);
                LDMX4(A[f][0], A[f][1], A[f][2], A[f][3], smb + OFF_ALO + a);
            }
#pragma unroll
            for (int f = 0; f < 8; f++) {
                MMA16816(C[f][0], A[f], Bh[ks][0]);
                MMA16816(C[f][1], A[f], Bh[ks][1]);
            }
        }

        // ---- epilogue: partial z . tanh(C + P) per warp slice ----
        const int mb = t * 128;
#pragma unroll
        for (int f = 0; f < 8; f++) {
            const int r0 = f * 16 + (l >> 2), r1 = r0 + 8;
            const int s0 = (mb + r0) % Sc, s1 = (mb + r1) % Sc;
            float2 p00 = __ldg((const float2*)&g_P[s0 * Hc + c0]);
            float2 p01 = __ldg((const float2*)&g_P[s0 * Hc + c0 + 8]);
            float2 p10 = __ldg((const float2*)&g_P[s1 * Hc + c0]);
            float2 p11 = __ldg((const float2*)&g_P[s1 * Hc + c0 + 8]);
            float p0 = zv0 * tanh_fast(C[f][0][0] + p00.x) + zv1 * tanh_fast(C[f][0][1] + p00.y)
                     + zv2 * tanh_fast(C[f][1][0] + p01.x) + zv3 * tanh_fast(C[f][1][1] + p01.y);
            float p1 = zv0 * tanh_fast(C[f][0][2] + p10.x) + zv1 * tanh_fast(C[f][0][3] + p10.y)
                     + zv2 * tanh_fast(C[f][1][2] + p11.x) + zv3 * tanh_fast(C[f][1][3] + p11.y);
            p0 += __shfl_xor_sync(0xffffffffu, p0, 1);
            p0 += __shfl_xor_sync(0xffffffffu, p0, 2);
            p1 += __shfl_xor_sync(0xffffffffu, p1, 1);
            p1 += __shfl_xor_sync(0xffffffffu, p1, 2);
            if ((l & 3) == 0) { red[r0 * 9 + wid] = p0; red[r1 * 9 + wid] = p1; }
        }
        __syncthreads();
        if (tid < 128) {
            float s = 0.f;
#pragma unroll
            for (int w = 0; w < 8; w++) s += red[tid * 9 + w];
            g_scores[mb + tid] = s;
        }
        __syncthreads();
    }
}

// ===================== per-batch finalize (k3 fused via last-block) =====================
__global__ void k2_finalize(const float* __restrict__ X,
                            const void* __restrict__ mask,
                            const float* __restrict__ Xitem,
                            const float* __restrict__ origin,
                            float* __restrict__ out) {
    __shared__ float sh_attn[Sc];
    __shared__ __align__(16) float sh_outv[Dc];
    __shared__ __align__(16) float sh_ws[4 * Dc];
    __shared__ float sh_w[4];
    __shared__ float sh_red[16];
    __shared__ float sh_res[4];
    __shared__ int   sh_len;
    __shared__ int   sh_last;

    const int b = blockIdx.x, tid = threadIdx.x;
    const int w = tid >> 5, l = tid & 31;
    const int fl = g_flags;
    const int mode = (fl & 1) ? 2 : ((fl & 2) ? 1 : 0);

    int cnt = mask_at(mask, b * Sc + tid, mode);
    if (tid + 128 < Sc) cnt += mask_at(mask, b * Sc + tid + 128, mode);
#pragma unroll
    for (int o = 16; o; o >>= 1) cnt += __shfl_xor_sync(0xffffffffu, cnt, o);
    if (l == 0) sh_w[w] = (float)cnt;
    __syncthreads();
    if (tid == 0) sh_len = (int)(sh_w[0] + sh_w[1] + sh_w[2] + sh_w[3]);
    __syncthreads();
    const int len = sh_len;

    float sc0 = 0.f, sc1 = 0.f, m0 = -FLT_MAX;
    if (tid < len)       { sc0 = g_scores[b * Sc + tid];       m0 = sc0; }
    if (tid + 128 < len) { sc1 = g_scores[b * Sc + tid + 128]; m0 = fmaxf(m0, sc1); }
#pragma unroll
    for (int o = 16; o; o >>= 1) m0 = fmaxf(m0, __shfl_xor_sync(0xffffffffu, m0, o));
    __syncthreads();
    if (l == 0) sh_w[w] = m0;
    __syncthreads();
    const float mx = fmaxf(fmaxf(sh_w[0], sh_w[1]), fmaxf(sh_w[2], sh_w[3]));

    float e0 = (tid < len) ? expf(sc0 - mx) : 0.f;
    float e1 = (tid + 128 < len) ? expf(sc1 - mx) : 0.f;
    float ss = e0 + e1;
#pragma unroll
    for (int o = 16; o; o >>= 1) ss += __shfl_xor_sync(0xffffffffu, ss, o);
    __syncthreads();
    if (l == 0) sh_w[w] = ss;
    __syncthreads();
    const float inv = 1.f / (sh_w[0] + sh_w[1] + sh_w[2] + sh_w[3]);
    sh_attn[tid] = e0 * inv;
    if (tid + 128 < Sc) sh_attn[tid + 128] = e1 * inv;
    __syncthreads();

    // ---- weighted sum: warp w -> rows = w (mod 4), lane l -> d = 4l..4l+3 ----
    const float4* Xb4 = (const float4*)(X + (size_t)b * Sc * Dc) + l;
    float4 acc0 = make_float4(0.f, 0.f, 0.f, 0.f);
    float4 acc1 = make_float4(0.f, 0.f, 0.f, 0.f);
    int r = w;
    for (; r + 4 < len; r += 8) {
        const float aw0 = sh_attn[r], aw1 = sh_attn[r + 4];
        const float4 x0 = __ldg(&Xb4[(size_t)r * 32]);
        const float4 x1 = __ldg(&Xb4[(size_t)(r + 4) * 32]);
        acc0.x = fmaf(aw0, x0.x, acc0.x); acc0.y = fmaf(aw0, x0.y, acc0.y);
        acc0.z = fmaf(aw0, x0.z, acc0.z); acc0.w = fmaf(aw0, x0.w, acc0.w);
        acc1.x = fmaf(aw1, x1.x, acc1.x); acc1.y = fmaf(aw1, x1.y, acc1.y);
        acc1.z = fmaf(aw1, x1.z, acc1.z); acc1.w = fmaf(aw1, x1.w, acc1.w);
    }
    if (r < len) {
        const float aw = sh_attn[r];
        const float4 x0 = __ldg(&Xb4[(size_t)r * 32]);
        acc0.x = fmaf(aw, x0.x, acc0.x); acc0.y = fmaf(aw, x0.y, acc0.y);
        acc0.z = fmaf(aw, x0.z, acc0.z); acc0.w = fmaf(aw, x0.w, acc0.w);
    }
    acc0.x += acc1.x; acc0.y += acc1.y; acc0.z += acc1.z; acc0.w += acc1.w;
    *(float4*)&sh_ws[w * Dc + 4 * l] = acc0;
    __syncthreads();
    const float ao = sh_ws[tid] + sh_ws[Dc + tid] + sh_ws[2 * Dc + tid] + sh_ws[3 * Dc + tid];

    const float lastv = sh_attn[len - 1] * __ldg(&X[(size_t)b * Sc * Dc + (size_t)(len - 1) * Dc + tid]);
    const float outv = ao - lastv;
    sh_outv[tid] = outv;

    const float xi = __ldg(&Xitem[b * Dc + tid]);
    float r0 = lastv * lastv, r1 = outv * outv, r2 = lastv * outv, r3 = ao * xi;
#pragma unroll
    for (int o = 16; o; o >>= 1) {
        r0 += __shfl_xor_sync(0xffffffffu, r0, o);
        r1 += __shfl_xor_sync(0xffffffffu, r1, o);
        r2 += __shfl_xor_sync(0xffffffffu, r2, o);
        r3 += __shfl_xor_sync(0xffffffffu, r3, o);
    }
    if (l == 0) { sh_red[w] = r0; sh_red[4 + w] = r1; sh_red[8 + w] = r2; sh_red[12 + w] = r3; }
    __syncthreads();
    if (tid < 4)
        sh_res[tid] = sh_red[tid * 4] + sh_red[tid * 4 + 1] + sh_red[tid * 4 + 2] + sh_red[tid * 4 + 3];
    __syncthreads();

    const float normOut = sqrtf(fmaxf(sh_res[1], 1e-12f));

    out[b * (Dc + 1) + tid] = ao;
    if (tid == 0) {
        out[b * (Dc + 1) + Dc] = sh_res[3];
        const float cosp = sh_res[2] / (sqrtf(fmaxf(sh_res[0], 1e-12f)) * normOut);
        const float pl = (1.f - cosp) * 0.5f;
        g_posloss[b] = softplus_f(-pl);
    }

    const float o0 = sh_outv[4 * l], o1 = sh_outv[4 * l + 1];
    const float o2 = sh_outv[4 * l + 2], o3 = sh_outv[4 * l + 3];
    const float4* Ob = (const float4*)(origin + (size_t)b * Nc * Dc);
    float nloss = 0.f;
    for (int n = w; n < Nc; n += 4) {
        const float4 og = Ob[n * 32 + l];
        float dot = og.x * o0 + og.y * o1 + og.z * o2 + og.w * o3;
        float nn = og.x * og.x + og.y * og.y + og.z * og.z + og.w * og.w;
#pragma unroll
        for (int o = 16; o; o >>= 1) {
            dot += __shfl_xor_sync(0xffffffffu, dot, o);
            nn  += __shfl_xor_sync(0xffffffffu, nn, o);
        }
        const float cosn = dot / (sqrtf(fmaxf(nn, 1e-12f)) * normOut);
        nloss += softplus_f((1.f - cosn) * 0.5f);
    }
    __syncthreads();
    if (l == 0) sh_w[w] = nloss;
    __syncthreads();
    if (tid == 0) g_negsum[b] = sh_w[0] + sh_w[1] + sh_w[2] + sh_w[3];

    // ---- last-block aux finalization (fused k3) ----
    __threadfence();
    __syncthreads();
    if (tid == 0) sh_last = (atomicAdd(&g_done, 1) == Bc - 1);
    __syncthreads();
    if (sh_last) {
        __threadfence();
        // block-sum of all 1024 posloss values (128 threads x 8)
        float v = 0.f;
#pragma unroll
        for (int j = 0; j < 8; j++) v += g_posloss[tid + j * 128];
#pragma unroll
        for (int o = 16; o; o >>= 1) v += __shfl_xor_sync(0xffffffffu, v, o);
        if (l == 0) sh_w[w] = v;
        __syncthreads();
        const float tot = sh_w[0] + sh_w[1] + sh_w[2] + sh_w[3];
#pragma unroll
        for (int j = 0; j < 8; j++) {
            const int bb = tid + j * 128;
            out[OUT_CONCAT + bb] = tot + g_negsum[bb];
        }
        if (tid == 0) { g_done = 0; g_flags = 0; }
    }
}

extern "C" void kernel_launch(void* const* d_in, const int* in_sizes, int n_in,
                              void* d_out, int out_size) {
    const float* X      = (const float*)d_in[0];
    const float* pos    = (const float*)d_in[1];
    const float* Xitem  = (const float*)d_in[2];
    const void*  mask   = d_in[3];
    const float* origin = (const float*)d_in[4];
    const float* Wp     = (const float*)d_in[5];
    const float* We     = (const float*)d_in[6];
    const float* z      = (const float*)d_in[7];
    float* out = (float*)d_out;

    cudaFuncSetAttribute(k1_mma, cudaFuncAttributeMaxDynamicSharedMemorySize, SMEM_K1);

    k0_P<<<Sc, Hc>>>(pos, Wp, (const uint4*)mask);
    k1_mma<<<296, 256, SMEM_K1>>>(X, We, z);
    k2_finalize<<<Bc, Dc>>>(X, mask, Xitem, origin, out);
}

// round 9
// speedup vs baseline: 1.2426x; 1.2426x over previous
#include <cuda_runtime.h>
#include <cuda_bf16.h>
#include <float.h>
#include <math.h>
#include <cstdint>

// Problem constants
constexpr int Bc = 1024;
constexpr int Sc = 200;
constexpr int Dc = 128;
constexpr int Hc = 128;
constexpr int Nc = 64;
constexpr int ROWS = Bc * Sc;             // 204800
constexpr int TILES = ROWS / 128;         // 1600
constexpr int OUT_CONCAT = Bc * (Dc + 1); // 132096

// Scratch
__device__ float g_P[Sc * Hc];
__device__ float g_scores[ROWS];
__device__ float g_posloss[Bc];
__device__ float g_negsum[Bc];
__device__ int   g_flags = 0;   // bit0 = bad (uint8), bit1 = f32
__device__ int   g_done  = 0;   // k2 completion counter

__device__ __forceinline__ uint32_t smem_u32(const void* p) {
    uint32_t a;
    asm("{ .reg .u64 t; cvta.to.shared.u64 t, %1; cvt.u32.u64 %0, t; }" : "=r"(a) : "l"(p));
    return a;
}

#define LDMX4(r0, r1, r2, r3, addr) \
    asm volatile("ldmatrix.sync.aligned.m8n8.x4.shared.b16 {%0,%1,%2,%3}, [%4];" \
        : "=r"(r0), "=r"(r1), "=r"(r2), "=r"(r3) : "r"(addr))
#define LDMX2(r0, r1, addr) \
    asm volatile("ldmatrix.sync.aligned.m8n8.x2.shared.b16 {%0,%1}, [%2];" \
        : "=r"(r0), "=r"(r1) : "r"(addr))
#define MMA16816(c, a, b) \
    asm volatile("mma.sync.aligned.m16n8k16.row.col.f32.bf16.bf16.f32 " \
        "{%0,%1,%2,%3},{%4,%5,%6,%7},{%8,%9},{%0,%1,%2,%3};" \
        : "+f"((c)[0]), "+f"((c)[1]), "+f"((c)[2]), "+f"((c)[3]) \
        : "r"((a)[0]), "r"((a)[1]), "r"((a)[2]), "r"((a)[3]), "r"((b)[0]), "r"((b)[1]))

__device__ __forceinline__ uint32_t swz(int row, int chunk) {
    return (uint32_t)(row * 256 + ((chunk ^ (row & 7)) << 4));
}

__device__ __forceinline__ float softplus_f(float x) {
    return fmaxf(x, 0.f) + log1pf(expf(-fabsf(x)));
}
__device__ __forceinline__ float tanh_fast(float x) {
    float t;
    asm("tanh.approx.f32 %0, %1;" : "=f"(t) : "f"(x));
    return t;
}
__device__ __forceinline__ int mask_at(const void* m, int idx, int mode) {
    if (mode == 2) return ((const unsigned char*)m)[idx] != 0;
    if (mode == 1) return ((const float*)m)[idx] != 0.f;
    return ((const int*)m)[idx] != 0;
}

// ===================== P rows + fused mask-dtype detection =====================
// grid = 100 blocks x 256 threads; each block computes 2 rows of P with 4-way ILP.
__global__ void k0_P(const float* __restrict__ pos, const float* __restrict__ Wp,
                     const uint4* __restrict__ mraw) {
    const int tid = threadIdx.x;
    const int s = blockIdx.x * 2 + (tid >> 7);
    const int h = tid & 127;
    const int i = blockIdx.x * 256 + tid;
    if (i < (Bc * Sc) / 16) {
        uint4 v = mraw[i];
        int fl = 0;
        uint32_t ws[4] = {v.x, v.y, v.z, v.w};
#pragma unroll
        for (int j = 0; j < 4; j++) {
            if (ws[j] == 0x3F800000u) fl |= 2;
            else if (ws[j] > 1u) fl |= 1;
        }
        if (fl) atomicOr(&g_flags, fl);
    }
    float a0 = 0.f, a1 = 0.f, a2 = 0.f, a3 = 0.f;
    const float* pr = pos + s * Dc;
    const float* wc = Wp + h;
#pragma unroll 8
    for (int d = 0; d < Dc; d += 4) {
        a0 = fmaf(__ldg(&pr[d + 0]), __ldg(&wc[(d + 0) * Hc]), a0);
        a1 = fmaf(__ldg(&pr[d + 1]), __ldg(&wc[(d + 1) * Hc]), a1);
        a2 = fmaf(__ldg(&pr[d + 2]), __ldg(&wc[(d + 2) * Hc]), a2);
        a3 = fmaf(__ldg(&pr[d + 3]), __ldg(&wc[(d + 3) * Hc]), a3);
    }
    g_P[s * Hc + h] = (a0 + a1) + (a2 + a3);
}

// ===================== mma.sync score kernel =====================
// Double-buffered bf16 tiles; convert of next tile interleaved into the GEMM.
constexpr int BUF = 65536;                       // hi(32K)+lo(32K) per buffer
constexpr int OFF_RED = 2 * BUF;                 // 131072; 128*9*4 = 4608
constexpr int SMEM_K1 = OFF_RED + 128 * 9 * 4;   // 135680

__device__ __forceinline__ void split4(float4 v, uint2& hh, uint2& ll) {
    uint32_t ux = __float_as_uint(v.x), uy = __float_as_uint(v.y);
    uint32_t uz = __float_as_uint(v.z), uw = __float_as_uint(v.w);
    hh.x = __byte_perm(ux, uy, 0x7632);
    hh.y = __byte_perm(uz, uw, 0x7632);
    float lx = v.x - __uint_as_float(ux & 0xFFFF0000u);
    float ly = v.y - __uint_as_float(uy & 0xFFFF0000u);
    float lz = v.z - __uint_as_float(uz & 0xFFFF0000u);
    float lw = v.w - __uint_as_float(uw & 0xFFFF0000u);
    asm("cvt.rn.bf16x2.f32 %0, %1, %2;" : "=r"(ll.x) : "f"(ly), "f"(lx));
    asm("cvt.rn.bf16x2.f32 %0, %1, %2;" : "=r"(ll.y) : "f"(lw), "f"(lz));
}

// convert chunk jj of pf into buffer at byte offset bufoff
__device__ __forceinline__ void conv_chunk(char* smc, int bufoff, const float4* pf,
                                           int jj, int tid) {
    int i4 = tid + jj * 256;
    int elem = i4 * 4;
    int row = elem >> 7, col = elem & 127;
    uint32_t a = swz(row, col >> 3) + (uint32_t)((col & 7) * 2);
    uint2 hh, ll;
    split4(pf[jj], hh, ll);
    *(uint2*)(smc + bufoff + a) = hh;
    *(uint2*)(smc + bufoff + 32768 + a) = ll;
}

__global__ void __launch_bounds__(256, 1)
k1_mma(const float* __restrict__ X, const float* __restrict__ We, const float* __restrict__ z) {
    extern __shared__ char smc[];
    const uint32_t smb = smem_u32(smc);
    float* red = (float*)(smc + OFF_RED);
    const int tid = threadIdx.x;
    const int wid = tid >> 5, l = tid & 31;
    const int bn = wid * 16;

    // ---- stage WeT hi/lo in buf0, load B fragments ----
    for (int i = tid; i < Dc * Hc; i += 256) {
        int d = i >> 7, h = i & 127;
        float v = We[i];
        __nv_bfloat16 hi = __float2bfloat16(v);
        __nv_bfloat16 lo = __float2bfloat16(v - __bfloat162float(hi));
        uint32_t a = swz(h, d >> 3) + (uint32_t)((d & 7) * 2);
        *(__nv_bfloat16*)(smc + a) = hi;
        *(__nv_bfloat16*)(smc + 32768 + a) = lo;
    }
    __syncthreads();

    uint32_t Bh[8][2][2], Bl[8][2][2];
    {
        const int brow = bn + (l & 7);
        const int bc = (l >> 3) & 1;
#pragma unroll
        for (int ks = 0; ks < 8; ks++) {
#pragma unroll
            for (int j = 0; j < 2; j++) {
                uint32_t a = swz(brow + j * 8, 2 * ks + bc);
                LDMX2(Bh[ks][j][0], Bh[ks][j][1], smb + a);
                LDMX2(Bl[ks][j][0], Bl[ks][j][1], smb + 32768 + a);
            }
        }
    }
    const int c0 = bn + (l & 3) * 2;
    const float zv0 = __ldg(&z[c0]),     zv1 = __ldg(&z[c0 + 1]);
    const float zv2 = __ldg(&z[c0 + 8]), zv3 = __ldg(&z[c0 + 9]);
    __syncthreads();

    const int arow_off = (l & 7) + ((l >> 3) & 1) * 8;
    const int achk_off = (l >> 4) & 1;

    const int GD = gridDim.x;
    int t = blockIdx.x;
    float4 pf[16];
    // prologue: tile t converted into buf0; pf <- raw tile t+GD
    if (t < TILES) {
        const float4* Xg = (const float4*)(X + (size_t)t * (128 * 128));
#pragma unroll
        for (int jj = 0; jj < 16; jj++) pf[jj] = Xg[tid + jj * 256];
#pragma unroll
        for (int jj = 0; jj < 16; jj++) conv_chunk(smc, 0, pf, jj, tid);
    }
    if (t + GD < TILES) {
        const float4* Xg = (const float4*)(X + (size_t)(t + GD) * (128 * 128));
#pragma unroll
        for (int jj = 0; jj < 16; jj++) pf[jj] = Xg[tid + jj * 256];
    }
    __syncthreads();

    int p = 0;
    for (; t < TILES; t += GD, p ^= 1) {
        const int curoff = p * BUF;
        const int nxtoff = (1 - p) * BUF;
        const bool havenext = (t + GD < TILES);

        // ---- GEMM on buf[p], interleaving convert of pf -> buf[1-p] ----
        float C[8][2][4];
#pragma unroll
        for (int f = 0; f < 8; f++)
#pragma unroll
            for (int j = 0; j < 2; j++)
#pragma unroll
                for (int q = 0; q < 4; q++) C[f][j][q] = 0.f;

#pragma unroll
        for (int ks = 0; ks < 8; ks++) {
            uint32_t A[8][4];
#pragma unroll
            for (int f = 0; f < 8; f++) {
                uint32_t a = swz(f * 16 + arow_off, 2 * ks + achk_off);
                LDMX4(A[f][0], A[f][1], A[f][2], A[f][3], smb + curoff + a);
            }
            // interleaved convert (fills ALU pipes while tensor pipe is busy)
            if (havenext) conv_chunk(smc, nxtoff, pf, 2 * ks, tid);
#pragma unroll
            for (int f = 0; f < 8; f++) {
                MMA16816(C[f][0], A[f], Bh[ks][0]);
                MMA16816(C[f][1], A[f], Bh[ks][1]);
                MMA16816(C[f][0], A[f], Bl[ks][0]);
                MMA16816(C[f][1], A[f], Bl[ks][1]);
            }
#pragma unroll
            for (int f = 0; f < 8; f++) {
                uint32_t a = swz(f * 16 + arow_off, 2 * ks + achk_off);
                LDMX4(A[f][0], A[f][1], A[f][2], A[f][3], smb + curoff + 32768 + a);
            }
            if (havenext) conv_chunk(smc, nxtoff, pf, 2 * ks + 1, tid);
#pragma unroll
            for (int f = 0; f < 8; f++) {
                MMA16816(C[f][0], A[f], Bh[ks][0]);
                MMA16816(C[f][1], A[f], Bh[ks][1]);
            }
        }

        // ---- prefetch raw tile t+2*GD into pf (hidden by epilogue + next GEMM) ----
        if (t + 2 * GD < TILES) {
            const float4* Xg = (const float4*)(X + (size_t)(t + 2 * GD) * (128 * 128));
#pragma unroll
            for (int jj = 0; jj < 16; jj++) pf[jj] = Xg[tid + jj * 256];
        }

        // ---- epilogue: partial z . tanh(C + P) per warp slice ----
        const int mb = t * 128;
#pragma unroll
        for (int f = 0; f < 8; f++) {
            const int r0 = f * 16 + (l >> 2), r1 = r0 + 8;
            const int s0 = (mb + r0) % Sc, s1 = (mb + r1) % Sc;
            float2 p00 = __ldg((const float2*)&g_P[s0 * Hc + c0]);
            float2 p01 = __ldg((const float2*)&g_P[s0 * Hc + c0 + 8]);
            float2 p10 = __ldg((const float2*)&g_P[s1 * Hc + c0]);
            float2 p11 = __ldg((const float2*)&g_P[s1 * Hc + c0 + 8]);
            float p0 = zv0 * tanh_fast(C[f][0][0] + p00.x) + zv1 * tanh_fast(C[f][0][1] + p00.y)
                     + zv2 * tanh_fast(C[f][1][0] + p01.x) + zv3 * tanh_fast(C[f][1][1] + p01.y);
            float p1 = zv0 * tanh_fast(C[f][0][2] + p10.x) + zv1 * tanh_fast(C[f][0][3] + p10.y)
                     + zv2 * tanh_fast(C[f][1][2] + p11.x) + zv3 * tanh_fast(C[f][1][3] + p11.y);
            p0 += __shfl_xor_sync(0xffffffffu, p0, 1);
            p0 += __shfl_xor_sync(0xffffffffu, p0, 2);
            p1 += __shfl_xor_sync(0xffffffffu, p1, 1);
            p1 += __shfl_xor_sync(0xffffffffu, p1, 2);
            if ((l & 3) == 0) { red[r0 * 9 + wid] = p0; red[r1 * 9 + wid] = p1; }
        }
        __syncthreads();
        if (tid < 128) {
            float s = 0.f;
#pragma unroll
            for (int w = 0; w < 8; w++) s += red[tid * 9 + w];
            g_scores[mb + tid] = s;
        }
        __syncthreads();   // also orders conv stores to buf[1-p] before next GEMM
    }
}

// ===================== per-batch finalize (aux fused via last-block) =====================
__global__ void k2_finalize(const float* __restrict__ X,
                            const void* __restrict__ mask,
                            const float* __restrict__ Xitem,
                            const float* __restrict__ origin,
                            float* __restrict__ out) {
    __shared__ float sh_attn[Sc];
    __shared__ __align__(16) float sh_outv[Dc];
    __shared__ __align__(16) float sh_ws[4 * Dc];
    __shared__ float sh_w[4];
    __shared__ float sh_red[16];
    __shared__ float sh_res[4];
    __shared__ int   sh_len;
    __shared__ int   sh_last;

    const int b = blockIdx.x, tid = threadIdx.x;
    const int w = tid >> 5, l = tid & 31;
    const int fl = g_flags;
    const int mode = (fl & 1) ? 2 : ((fl & 2) ? 1 : 0);

    int cnt = mask_at(mask, b * Sc + tid, mode);
    if (tid + 128 < Sc) cnt += mask_at(mask, b * Sc + tid + 128, mode);
#pragma unroll
    for (int o = 16; o; o >>= 1) cnt += __shfl_xor_sync(0xffffffffu, cnt, o);
    if (l == 0) sh_w[w] = (float)cnt;
    __syncthreads();
    if (tid == 0) sh_len = (int)(sh_w[0] + sh_w[1] + sh_w[2] + sh_w[3]);
    __syncthreads();
    const int len = sh_len;

    float sc0 = 0.f, sc1 = 0.f, m0 = -FLT_MAX;
    if (tid < len)       { sc0 = g_scores[b * Sc + tid];       m0 = sc0; }
    if (tid + 128 < len) { sc1 = g_scores[b * Sc + tid + 128]; m0 = fmaxf(m0, sc1); }
#pragma unroll
    for (int o = 16; o; o >>= 1) m0 = fmaxf(m0, __shfl_xor_sync(0xffffffffu, m0, o));
    __syncthreads();
    if (l == 0) sh_w[w] = m0;
    __syncthreads();
    const float mx = fmaxf(fmaxf(sh_w[0], sh_w[1]), fmaxf(sh_w[2], sh_w[3]));

    float e0 = (tid < len) ? expf(sc0 - mx) : 0.f;
    float e1 = (tid + 128 < len) ? expf(sc1 - mx) : 0.f;
    float ss = e0 + e1;
#pragma unroll
    for (int o = 16; o; o >>= 1) ss += __shfl_xor_sync(0xffffffffu, ss, o);
    __syncthreads();
    if (l == 0) sh_w[w] = ss;
    __syncthreads();
    const float inv = 1.f / (sh_w[0] + sh_w[1] + sh_w[2] + sh_w[3]);
    sh_attn[tid] = e0 * inv;
    if (tid + 128 < Sc) sh_attn[tid + 128] = e1 * inv;
    __syncthreads();

    // ---- weighted sum: warp w -> rows = w (mod 4), lane l -> d = 4l..4l+3 ----
    const float4* Xb4 = (const float4*)(X + (size_t)b * Sc * Dc) + l;
    float4 acc0 = make_float4(0.f, 0.f, 0.f, 0.f);
    float4 acc1 = make_float4(0.f, 0.f, 0.f, 0.f);
    int r = w;
    for (; r + 4 < len; r += 8) {
        const float aw0 = sh_attn[r], aw1 = sh_attn[r + 4];
        const float4 x0 = __ldg(&Xb4[(size_t)r * 32]);
        const float4 x1 = __ldg(&Xb4[(size_t)(r + 4) * 32]);
        acc0.x = fmaf(aw0, x0.x, acc0.x); acc0.y = fmaf(aw0, x0.y, acc0.y);
        acc0.z = fmaf(aw0, x0.z, acc0.z); acc0.w = fmaf(aw0, x0.w, acc0.w);
        acc1.x = fmaf(aw1, x1.x, acc1.x); acc1.y = fmaf(aw1, x1.y, acc1.y);
        acc1.z = fmaf(aw1, x1.z, acc1.z); acc1.w = fmaf(aw1, x1.w, acc1.w);
    }
    if (r < len) {
        const float aw = sh_attn[r];
        const float4 x0 = __ldg(&Xb4[(size_t)r * 32]);
        acc0.x = fmaf(aw, x0.x, acc0.x); acc0.y = fmaf(aw, x0.y, acc0.y);
        acc0.z = fmaf(aw, x0.z, acc0.z); acc0.w = fmaf(aw, x0.w, acc0.w);
    }
    acc0.x += acc1.x; acc0.y += acc1.y; acc0.z += acc1.z; acc0.w += acc1.w;
    *(float4*)&sh_ws[w * Dc + 4 * l] = acc0;
    __syncthreads();
    const float ao = sh_ws[tid] + sh_ws[Dc + tid] + sh_ws[2 * Dc + tid] + sh_ws[3 * Dc + tid];

    const float lastv = sh_attn[len - 1] * __ldg(&X[(size_t)b * Sc * Dc + (size_t)(len - 1) * Dc + tid]);
    const float outv = ao - lastv;
    sh_outv[tid] = outv;

    const float xi = __ldg(&Xitem[b * Dc + tid]);
    float r0 = lastv * lastv, r1 = outv * outv, r2 = lastv * outv, r3 = ao * xi;
#pragma unroll
    for (int o = 16; o; o >>= 1) {
        r0 += __shfl_xor_sync(0xffffffffu, r0, o);
        r1 += __shfl_xor_sync(0xffffffffu, r1, o);
        r2 += __shfl_xor_sync(0xffffffffu, r2, o);
        r3 += __shfl_xor_sync(0xffffffffu, r3, o);
    }
    if (l == 0) { sh_red[w] = r0; sh_red[4 + w] = r1; sh_red[8 + w] = r2; sh_red[12 + w] = r3; }
    __syncthreads();
    if (tid < 4)
        sh_res[tid] = sh_red[tid * 4] + sh_red[tid * 4 + 1] + sh_red[tid * 4 + 2] + sh_red[tid * 4 + 3];
    __syncthreads();

    const float normOut = sqrtf(fmaxf(sh_res[1], 1e-12f));

    out[b * (Dc + 1) + tid] = ao;
    if (tid == 0) {
        out[b * (Dc + 1) + Dc] = sh_res[3];
        const float cosp = sh_res[2] / (sqrtf(fmaxf(sh_res[0], 1e-12f)) * normOut);
        const float pl = (1.f - cosp) * 0.5f;
        g_posloss[b] = softplus_f(-pl);
    }

    const float o0 = sh_outv[4 * l], o1 = sh_outv[4 * l + 1];
    const float o2 = sh_outv[4 * l + 2], o3 = sh_outv[4 * l + 3];
    const float4* Ob = (const float4*)(origin + (size_t)b * Nc * Dc);
    float nloss = 0.f;
    for (int n = w; n < Nc; n += 4) {
        const float4 og = Ob[n * 32 + l];
        float dot = og.x * o0 + og.y * o1 + og.z * o2 + og.w * o3;
        float nn = og.x * og.x + og.y * og.y + og.z * og.z + og.w * og.w;
#pragma unroll
        for (int o = 16; o; o >>= 1) {
            dot += __shfl_xor_sync(0xffffffffu, dot, o);
            nn  += __shfl_xor_sync(0xffffffffu, nn, o);
        }
        const float cosn = dot / (sqrtf(fmaxf(nn, 1e-12f)) * normOut);
        nloss += softplus_f((1.f - cosn) * 0.5f);
    }
    __syncthreads();
    if (l == 0) sh_w[w] = nloss;
    __syncthreads();
    if (tid == 0) g_negsum[b] = sh_w[0] + sh_w[1] + sh_w[2] + sh_w[3];

    // ---- last-block aux finalization ----
    __threadfence();
    __syncthreads();
    if (tid == 0) sh_last = (atomicAdd(&g_done, 1) == Bc - 1);
    __syncthreads();
    if (sh_last) {
        __threadfence();
        float v = 0.f;
#pragma unroll
        for (int j = 0; j < 8; j++) v += g_posloss[tid + j * 128];
#pragma unroll
        for (int o = 16; o; o >>= 1) v += __shfl_xor_sync(0xffffffffu, v, o);
        if (l == 0) sh_w[w] = v;
        __syncthreads();
        const float tot = sh_w[0] + sh_w[1] + sh_w[2] + sh_w[3];
#pragma unroll
        for (int j = 0; j < 8; j++) {
            const int bb = tid + j * 128;
            out[OUT_CONCAT + bb] = tot + g_negsum[bb];
        }
        if (tid == 0) { g_done = 0; g_flags = 0; }
    }
}

extern "C" void kernel_launch(void* const* d_in, const int* in_sizes, int n_in,
                              void* d_out, int out_size) {
    const float* X      = (const float*)d_in[0];
    const float* pos    = (const float*)d_in[1];
    const float* Xitem  = (const float*)d_in[2];
    const void*  mask   = d_in[3];
    const float* origin = (const float*)d_in[4];
    const float* Wp     = (const float*)d_in[5];
    const float* We     = (const float*)d_in[6];
    const float* z      = (const float*)d_in[7];
    float* out = (float*)d_out;

    cudaFuncSetAttribute(k1_mma, cudaFuncAttributeMaxDynamicSharedMemorySize, SMEM_K1);

    k0_P<<<Sc / 2, 256>>>(pos, Wp, (const uint4*)mask);
    k1_mma<<<148, 256, SMEM_K1>>>(X, We, z);
    k2_finalize<<<Bc, Dc>>>(X, mask, Xitem, origin, out);
}

// round 11
// speedup vs baseline: 1.3661x; 1.0993x over previous
#include <cuda_runtime.h>
#include <cuda_bf16.h>
#include <float.h>
#include <math.h>
#include <cstdint>

// Problem constants
constexpr int Bc = 1024;
constexpr int Sc = 200;
constexpr int Dc = 128;
constexpr int Hc = 128;
constexpr int Nc = 64;
constexpr int ROWS = Bc * Sc;             // 204800
constexpr int TILES = ROWS / 128;         // 1600
constexpr int OUT_CONCAT = Bc * (Dc + 1); // 132096

// Scratch
__device__ float g_P[Sc * Hc];
__device__ float g_scores[ROWS];
__device__ float g_posloss[Bc];
__device__ float g_negsum[Bc];
__device__ int   g_flags = 0;   // bit0 = bad (uint8), bit1 = f32
__device__ int   g_done  = 0;   // k2 completion counter

__device__ __forceinline__ uint32_t smem_u32(const void* p) {
    uint32_t a;
    asm("{ .reg .u64 t; cvta.to.shared.u64 t, %1; cvt.u32.u64 %0, t; }" : "=r"(a) : "l"(p));
    return a;
}

#define LDMX4(r0, r1, r2, r3, addr) \
    asm volatile("ldmatrix.sync.aligned.m8n8.x4.shared.b16 {%0,%1,%2,%3}, [%4];" \
        : "=r"(r0), "=r"(r1), "=r"(r2), "=r"(r3) : "r"(addr))
#define LDMX2(r0, r1, addr) \
    asm volatile("ldmatrix.sync.aligned.m8n8.x2.shared.b16 {%0,%1}, [%2];" \
        : "=r"(r0), "=r"(r1) : "r"(addr))
#define MMA16816(c, a, b) \
    asm volatile("mma.sync.aligned.m16n8k16.row.col.f32.bf16.bf16.f32 " \
        "{%0,%1,%2,%3},{%4,%5,%6,%7},{%8,%9},{%0,%1,%2,%3};" \
        : "+f"((c)[0]), "+f"((c)[1]), "+f"((c)[2]), "+f"((c)[3]) \
        : "r"((a)[0]), "r"((a)[1]), "r"((a)[2]), "r"((a)[3]), "r"((b)[0]), "r"((b)[1]))

__device__ __forceinline__ uint32_t swz(int row, int chunk) {
    return (uint32_t)(row * 256 + ((chunk ^ (row & 7)) << 4));
}

__device__ __forceinline__ float softplus_f(float x) {
    return fmaxf(x, 0.f) + log1pf(expf(-fabsf(x)));
}
__device__ __forceinline__ float tanh_fast(float x) {
    float t;
    asm("tanh.approx.f32 %0, %1;" : "=f"(t) : "f"(x));
    return t;
}
__device__ __forceinline__ int mask_at(const void* m, int idx, int mode) {
    if (mode == 2) return ((const unsigned char*)m)[idx] != 0;
    if (mode == 1) return ((const float*)m)[idx] != 0.f;
    return ((const int*)m)[idx] != 0;
}

// ===================== P = pos @ Wp (SMEM-staged) + mask-dtype detection =====================
// 25 blocks x 1024 threads; each block: Wp (64KB) + 8 pos rows -> SMEM, computes 8 P rows.
constexpr int SMEM_K0 = (Dc * Hc + 8 * Dc) * 4;  // 69632 B

__global__ void __launch_bounds__(1024, 1)
k0_P(const float* __restrict__ pos, const float* __restrict__ Wp,
     const uint4* __restrict__ mraw) {
    extern __shared__ float sm0[];
    float* sWp  = sm0;             // [Dc*Hc]
    float* sPos = sm0 + Dc * Hc;   // [8*Dc]
    const int tid = threadIdx.x;

    // mask dtype scan: 12800 uint4 total
    const int i = blockIdx.x * 1024 + tid;
    if (i < (Bc * Sc) / 16) {
        uint4 v = mraw[i];
        int fl = 0;
        uint32_t ws[4] = {v.x, v.y, v.z, v.w};
#pragma unroll
        for (int j = 0; j < 4; j++) {
            if (ws[j] == 0x3F800000u) fl |= 2;
            else if (ws[j] > 1u) fl |= 1;
        }
        if (fl) atomicOr(&g_flags, fl);
    }

    // bulk-load Wp (4096 float4) and 8 pos rows (256 float4)
    const float4* w4 = (const float4*)Wp;
    float4* sW4 = (float4*)sWp;
#pragma unroll
    for (int j = 0; j < 4; j++) sW4[tid + j * 1024] = w4[tid + j * 1024];
    const int rbase = blockIdx.x * 8;
    if (tid < 256) {
        const int r = tid >> 5, c = tid & 31;
        ((float4*)sPos)[tid] = ((const float4*)(pos + (size_t)(rbase + r) * Dc))[c];
    }
    __syncthreads();

    const int lr = tid >> 7, h = tid & 127;
    const float* pr = sPos + lr * Dc;
    float a0 = 0.f, a1 = 0.f, a2 = 0.f, a3 = 0.f;
#pragma unroll 8
    for (int d = 0; d < Dc; d += 4) {
        a0 = fmaf(pr[d + 0], sWp[(d + 0) * Hc + h], a0);
        a1 = fmaf(pr[d + 1], sWp[(d + 1) * Hc + h], a1);
        a2 = fmaf(pr[d + 2], sWp[(d + 2) * Hc + h], a2);
        a3 = fmaf(pr[d + 3], sWp[(d + 3) * Hc + h], a3);
    }
    g_P[(rbase + lr) * Hc + h] = (a0 + a1) + (a2 + a3);
}

// ===================== mma.sync score kernel (R5 version) =====================
constexpr int OFF_AHI = 0;
constexpr int OFF_ALO = 32768;
constexpr int OFF_RED = 65536;                  // 128*9*4 = 4608
constexpr int SMEM_K1 = OFF_RED + 128 * 9 * 4;  // 70144

__device__ __forceinline__ void split4(float4 v, uint2& hh, uint2& ll) {
    uint32_t ux = __float_as_uint(v.x), uy = __float_as_uint(v.y);
    uint32_t uz = __float_as_uint(v.z), uw = __float_as_uint(v.w);
    hh.x = __byte_perm(ux, uy, 0x7632);
    hh.y = __byte_perm(uz, uw, 0x7632);
    float lx = v.x - __uint_as_float(ux & 0xFFFF0000u);
    float ly = v.y - __uint_as_float(uy & 0xFFFF0000u);
    float lz = v.z - __uint_as_float(uz & 0xFFFF0000u);
    float lw = v.w - __uint_as_float(uw & 0xFFFF0000u);
    asm("cvt.rn.bf16x2.f32 %0, %1, %2;" : "=r"(ll.x) : "f"(ly), "f"(lx));
    asm("cvt.rn.bf16x2.f32 %0, %1, %2;" : "=r"(ll.y) : "f"(lw), "f"(lz));
}

__global__ void __launch_bounds__(256, 1)
k1_mma(const float* __restrict__ X, const float* __restrict__ We, const float* __restrict__ z) {
    extern __shared__ char smc[];
    const uint32_t smb = smem_u32(smc);
    float* red = (float*)(smc + OFF_RED);
    const int tid = threadIdx.x;
    const int wid = tid >> 5, l = tid & 31;
    const int bn = wid * 16;

    // ---- stage WeT hi/lo, load B fragments ----
    for (int i = tid; i < Dc * Hc; i += 256) {
        int d = i >> 7, h = i & 127;
        float v = We[i];
        __nv_bfloat16 hi = __float2bfloat16(v);
        __nv_bfloat16 lo = __float2bfloat16(v - __bfloat162float(hi));
        uint32_t a = swz(h, d >> 3) + (uint32_t)((d & 7) * 2);
        *(__nv_bfloat16*)(smc + OFF_AHI + a) = hi;
        *(__nv_bfloat16*)(smc + OFF_ALO + a) = lo;
    }
    __syncthreads();

    uint32_t Bh[8][2][2], Bl[8][2][2];
    {
        const int brow = bn + (l & 7);
        const int bc = (l >> 3) & 1;
#pragma unroll
        for (int ks = 0; ks < 8; ks++) {
#pragma unroll
            for (int j = 0; j < 2; j++) {
                uint32_t a = swz(brow + j * 8, 2 * ks + bc);
                LDMX2(Bh[ks][j][0], Bh[ks][j][1], smb + OFF_AHI + a);
                LDMX2(Bl[ks][j][0], Bl[ks][j][1], smb + OFF_ALO + a);
            }
        }
    }
    const int c0 = bn + (l & 3) * 2;
    const float zv0 = __ldg(&z[c0]),     zv1 = __ldg(&z[c0 + 1]);
    const float zv2 = __ldg(&z[c0 + 8]), zv3 = __ldg(&z[c0 + 9]);
    __syncthreads();

    const int arow_off = (l & 7) + ((l >> 3) & 1) * 8;
    const int achk_off = (l >> 4) & 1;

    const int GD = gridDim.x;
    int t = blockIdx.x;
    float4 pf[16];
    if (t < TILES) {
        const float4* Xg = (const float4*)(X + (size_t)t * (128 * 128));
#pragma unroll
        for (int jj = 0; jj < 16; jj++) pf[jj] = Xg[tid + jj * 256];
    }

    for (; t < TILES; t += GD) {
        // ---- convert + store prefetched tile ----
#pragma unroll
        for (int jj = 0; jj < 16; jj++) {
            int i4 = tid + jj * 256;
            int elem = i4 * 4;
            int row = elem >> 7, col = elem & 127;
            uint32_t a = swz(row, col >> 3) + (uint32_t)((col & 7) * 2);
            uint2 hh, ll;
            split4(pf[jj], hh, ll);
            *(uint2*)(smc + OFF_AHI + a) = hh;
            *(uint2*)(smc + OFF_ALO + a) = ll;
        }
        __syncthreads();

        // ---- prefetch next tile (hidden behind GEMM) ----
        const int tn = t + GD;
        if (tn < TILES) {
            const float4* Xg = (const float4*)(X + (size_t)tn * (128 * 128));
#pragma unroll
            for (int jj = 0; jj < 16; jj++) pf[jj] = Xg[tid + jj * 256];
        }

        // ---- GEMM: C = Xhi*Whi + Xhi*Wlo + Xlo*Whi ----
        float C[8][2][4];
#pragma unroll
        for (int f = 0; f < 8; f++)
#pragma unroll
            for (int j = 0; j < 2; j++)
#pragma unroll
                for (int q = 0; q < 4; q++) C[f][j][q] = 0.f;

#pragma unroll
        for (int ks = 0; ks < 8; ks++) {
            uint32_t A[8][4];
#pragma unroll
            for (int f = 0; f < 8; f++) {
                uint32_t a = swz(f * 16 + arow_off, 2 * ks + achk_off);
                LDMX4(A[f][0], A[f][1], A[f][2], A[f][3], smb + OFF_AHI + a);
            }
#pragma unroll
            for (int f = 0; f < 8; f++) {
                MMA16816(C[f][0], A[f], Bh[ks][0]);
                MMA16816(C[f][1], A[f], Bh[ks][1]);
                MMA16816(C[f][0], A[f], Bl[ks][0]);
                MMA16816(C[f][1], A[f], Bl[ks][1]);
            }
#pragma unroll
            for (int f = 0; f < 8; f++) {
                uint32_t a = swz(f * 16 + arow_off, 2 * ks + achk_off);
                LDMX4(A[f][0], A[f][1], A[f][2], A[f][3], smb + OFF_ALO + a);
            }
#pragma unroll
            for (int f = 0; f < 8; f++) {
                MMA16816(C[f][0], A[f], Bh[ks][0]);
                MMA16816(C[f][1], A[f], Bh[ks][1]);
            }
        }

        // ---- epilogue: partial z . tanh(C + P) per warp slice ----
        const int mb = t * 128;
#pragma unroll
        for (int f = 0; f < 8; f++) {
            const int r0 = f * 16 + (l >> 2), r1 = r0 + 8;
            const int s0 = (mb + r0) % Sc, s1 = (mb + r1) % Sc;
            float2 p00 = __ldg((const float2*)&g_P[s0 * Hc + c0]);
            float2 p01 = __ldg((const float2*)&g_P[s0 * Hc + c0 + 8]);
            float2 p10 = __ldg((const float2*)&g_P[s1 * Hc + c0]);
            float2 p11 = __ldg((const float2*)&g_P[s1 * Hc + c0 + 8]);
            float p0 = zv0 * tanh_fast(C[f][0][0] + p00.x) + zv1 * tanh_fast(C[f][0][1] + p00.y)
                     + zv2 * tanh_fast(C[f][1][0] + p01.x) + zv3 * tanh_fast(C[f][1][1] + p01.y);
            float p1 = zv0 * tanh_fast(C[f][0][2] + p10.x) + zv1 * tanh_fast(C[f][0][3] + p10.y)
                     + zv2 * tanh_fast(C[f][1][2] + p11.x) + zv3 * tanh_fast(C[f][1][3] + p11.y);
            p0 += __shfl_xor_sync(0xffffffffu, p0, 1);
            p0 += __shfl_xor_sync(0xffffffffu, p0, 2);
            p1 += __shfl_xor_sync(0xffffffffu, p1, 1);
            p1 += __shfl_xor_sync(0xffffffffu, p1, 2);
            if ((l & 3) == 0) { red[r0 * 9 + wid] = p0; red[r1 * 9 + wid] = p1; }
        }
        __syncthreads();
        if (tid < 128) {
            float s = 0.f;
#pragma unroll
            for (int w = 0; w < 8; w++) s += red[tid * 9 + w];
            g_scores[mb + tid] = s;
        }
        __syncthreads();
    }
}

// ===================== per-batch finalize (aux fused via last-block) =====================
__global__ void k2_finalize(const float* __restrict__ X,
                            const void* __restrict__ mask,
                            const float* __restrict__ Xitem,
                            const float* __restrict__ origin,
                            float* __restrict__ out) {
    __shared__ float sh_attn[Sc];
    __shared__ __align__(16) float sh_outv[Dc];
    __shared__ __align__(16) float sh_ws[4 * Dc];
    __shared__ float sh_w[4];
    __shared__ float sh_red[16];
    __shared__ float sh_res[4];
    __shared__ int   sh_len;
    __shared__ int   sh_last;

    const int b = blockIdx.x, tid = threadIdx.x;
    const int w = tid >> 5, l = tid & 31;
    const int fl = g_flags;
    const int mode = (fl & 1) ? 2 : ((fl & 2) ? 1 : 0);

    int cnt = mask_at(mask, b * Sc + tid, mode);
    if (tid + 128 < Sc) cnt += mask_at(mask, b * Sc + tid + 128, mode);
#pragma unroll
    for (int o = 16; o; o >>= 1) cnt += __shfl_xor_sync(0xffffffffu, cnt, o);
    if (l == 0) sh_w[w] = (float)cnt;
    __syncthreads();
    if (tid == 0) sh_len = (int)(sh_w[0] + sh_w[1] + sh_w[2] + sh_w[3]);
    __syncthreads();
    const int len = sh_len;

    float sc0 = 0.f, sc1 = 0.f, m0 = -FLT_MAX;
    if (tid < len)       { sc0 = g_scores[b * Sc + tid];       m0 = sc0; }
    if (tid + 128 < len) { sc1 = g_scores[b * Sc + tid + 128]; m0 = fmaxf(m0, sc1); }
#pragma unroll
    for (int o = 16; o; o >>= 1) m0 = fmaxf(m0, __shfl_xor_sync(0xffffffffu, m0, o));
    __syncthreads();
    if (l == 0) sh_w[w] = m0;
    __syncthreads();
    const float mx = fmaxf(fmaxf(sh_w[0], sh_w[1]), fmaxf(sh_w[2], sh_w[3]));

    float e0 = (tid < len) ? expf(sc0 - mx) : 0.f;
    float e1 = (tid + 128 < len) ? expf(sc1 - mx) : 0.f;
    float ss = e0 + e1;
#pragma unroll
    for (int o = 16; o; o >>= 1) ss += __shfl_xor_sync(0xffffffffu, ss, o);
    __syncthreads();
    if (l == 0) sh_w[w] = ss;
    __syncthreads();
    const float inv = 1.f / (sh_w[0] + sh_w[1] + sh_w[2] + sh_w[3]);
    sh_attn[tid] = e0 * inv;
    if (tid + 128 < Sc) sh_attn[tid + 128] = e1 * inv;
    __syncthreads();

    // ---- weighted sum: warp w -> rows = w (mod 4), lane l -> d = 4l..4l+3 ----
    const float4* Xb4 = (const float4*)(X + (size_t)b * Sc * Dc) + l;
    float4 acc0 = make_float4(0.f, 0.f, 0.f, 0.f);
    float4 acc1 = make_float4(0.f, 0.f, 0.f, 0.f);
    int r = w;
    for (; r + 4 < len; r += 8) {
        const float aw0 = sh_attn[r], aw1 = sh_attn[r + 4];
        const float4 x0 = __ldg(&Xb4[(size_t)r * 32]);
        const float4 x1 = __ldg(&Xb4[(size_t)(r + 4) * 32]);
        acc0.x = fmaf(aw0, x0.x, acc0.x); acc0.y = fmaf(aw0, x0.y, acc0.y);
        acc0.z = fmaf(aw0, x0.z, acc0.z); acc0.w = fmaf(aw0, x0.w, acc0.w);
        acc1.x = fmaf(aw1, x1.x, acc1.x); acc1.y = fmaf(aw1, x1.y, acc1.y);
        acc1.z = fmaf(aw1, x1.z, acc1.z); acc1.w = fmaf(aw1, x1.w, acc1.w);
    }
    if (r < len) {
        const float aw = sh_attn[r];
        const float4 x0 = __ldg(&Xb4[(size_t)r * 32]);
        acc0.x = fmaf(aw, x0.x, acc0.x); acc0.y = fmaf(aw, x0.y, acc0.y);
        acc0.z = fmaf(aw, x0.z, acc0.z); acc0.w = fmaf(aw, x0.w, acc0.w);
    }
    acc0.x += acc1.x; acc0.y += acc1.y; acc0.z += acc1.z; acc0.w += acc1.w;
    *(float4*)&sh_ws[w * Dc + 4 * l] = acc0;
    __syncthreads();
    const float ao = sh_ws[tid] + sh_ws[Dc + tid] + sh_ws[2 * Dc + tid] + sh_ws[3 * Dc + tid];

    const float lastv = sh_attn[len - 1] * __ldg(&X[(size_t)b * Sc * Dc + (size_t)(len - 1) * Dc + tid]);
    const float outv = ao - lastv;
    sh_outv[tid] = outv;

    const float xi = __ldg(&Xitem[b * Dc + tid]);
    float r0 = lastv * lastv, r1 = outv * outv, r2 = lastv * outv, r3 = ao * xi;
#pragma unroll
    for (int o = 16; o; o >>= 1) {
        r0 += __shfl_xor_sync(0xffffffffu, r0, o);
        r1 += __shfl_xor_sync(0xffffffffu, r1, o);
        r2 += __shfl_xor_sync(0xffffffffu, r2, o);
        r3 += __shfl_xor_sync(0xffffffffu, r3, o);
    }
    if (l == 0) { sh_red[w] = r0; sh_red[4 + w] = r1; sh_red[8 + w] = r2; sh_red[12 + w] = r3; }
    __syncthreads();
    if (tid < 4)
        sh_res[tid] = sh_red[tid * 4] + sh_red[tid * 4 + 1] + sh_red[tid * 4 + 2] + sh_red[tid * 4 + 3];
    __syncthreads();

    const float normOut = sqrtf(fmaxf(sh_res[1], 1e-12f));

    out[b * (Dc + 1) + tid] = ao;
    if (tid == 0) {
        out[b * (Dc + 1) + Dc] = sh_res[3];
        const float cosp = sh_res[2] / (sqrtf(fmaxf(sh_res[0], 1e-12f)) * normOut);
        const float pl = (1.f - cosp) * 0.5f;
        g_posloss[b] = softplus_f(-pl);
    }

    const float o0 = sh_outv[4 * l], o1 = sh_outv[4 * l + 1];
    const float o2 = sh_outv[4 * l + 2], o3 = sh_outv[4 * l + 3];
    const float4* Ob = (const float4*)(origin + (size_t)b * Nc * Dc);
    float nloss = 0.f;
    for (int n = w; n < Nc; n += 4) {
        const float4 og = Ob[n * 32 + l];
        float dot = og.x * o0 + og.y * o1 + og.z * o2 + og.w * o3;
        float nn = og.x * og.x + og.y * og.y + og.z * og.z + og.w * og.w;
#pragma unroll
        for (int o = 16; o; o >>= 1) {
            dot += __shfl_xor_sync(0xffffffffu, dot, o);
            nn  += __shfl_xor_sync(0xffffffffu, nn, o);
        }
        const float cosn = dot / (sqrtf(fmaxf(nn, 1e-12f)) * normOut);
        nloss += softplus_f((1.f - cosn) * 0.5f);
    }
    __syncthreads();
    if (l == 0) sh_w[w] = nloss;
    __syncthreads();
    if (tid == 0) g_negsum[b] = sh_w[0] + sh_w[1] + sh_w[2] + sh_w[3];

    // ---- last-block aux finalization ----
    __threadfence();
    __syncthreads();
    if (tid == 0) sh_last = (atomicAdd(&g_done, 1) == Bc - 1);
    __syncthreads();
    if (sh_last) {
        __threadfence();
        float v = 0.f;
#pragma unroll
        for (int j = 0; j < 8; j++) v += g_posloss[tid + j * 128];
#pragma unroll
        for (int o = 16; o; o >>= 1) v += __shfl_xor_sync(0xffffffffu, v, o);
        if (l == 0) sh_w[w] = v;
        __syncthreads();
        const float tot = sh_w[0] + sh_w[1] + sh_w[2] + sh_w[3];
#pragma unroll
        for (int j = 0; j < 8; j++) {
            const int bb = tid + j * 128;
            out[OUT_CONCAT + bb] = tot + g_negsum[bb];
        }
        if (tid == 0) { g_done = 0; g_flags = 0; }
    }
}

extern "C" void kernel_launch(void* const* d_in, const int* in_sizes, int n_in,
                              void* d_out, int out_size) {
    const float* X      = (const float*)d_in[0];
    const float* pos    = (const float*)d_in[1];
    const float* Xitem  = (const float*)d_in[2];
    const void*  mask   = d_in[3];
    const float* origin = (const float*)d_in[4];
    const float* Wp     = (const float*)d_in[5];
    const float* We     = (const float*)d_in[6];
    const float* z      = (const float*)d_in[7];
    float* out = (float*)d_out;

    cudaFuncSetAttribute(k0_P,   cudaFuncAttributeMaxDynamicSharedMemorySize, SMEM_K0);
    cudaFuncSetAttribute(k1_mma, cudaFuncAttributeMaxDynamicSharedMemorySize, SMEM_K1);

    k0_P<<<Sc / 8, 1024, SMEM_K0>>>(pos, Wp, (const uint4*)mask);
    k1_mma<<<148, 256, SMEM_K1>>>(X, We, z);
    k2_finalize<<<Bc, Dc>>>(X, mask, Xitem, origin, out);
}

// round 12
// speedup vs baseline: 1.5253x; 1.1166x over previous
#include <cuda_runtime.h>
#include <cuda_bf16.h>
#include <cuda_fp16.h>
#include <float.h>
#include <math.h>
#include <cstdint>

// Problem constants
constexpr int Bc = 1024;
constexpr int Sc = 200;
constexpr int Dc = 128;
constexpr int Hc = 128;
constexpr int Nc = 64;
constexpr int ROWS = Bc * Sc;             // 204800
constexpr int TILES = ROWS / 128;         // 1600
constexpr int OUT_CONCAT = Bc * (Dc + 1); // 132096

// Scratch
__device__ float g_P[Sc * Hc];
__device__ float g_scores[ROWS];
__device__ float g_posloss[Bc];
__device__ float g_negsum[Bc];
__device__ int   g_flags = 0;   // bit0 = bad (uint8), bit1 = f32
__device__ int   g_done  = 0;   // k2 completion counter

__device__ __forceinline__ uint32_t smem_u32(const void* p) {
    uint32_t a;
    asm("{ .reg .u64 t; cvta.to.shared.u64 t, %1; cvt.u32.u64 %0, t; }" : "=r"(a) : "l"(p));
    return a;
}

#define LDMX4(r0, r1, r2, r3, addr) \
    asm volatile("ldmatrix.sync.aligned.m8n8.x4.shared.b16 {%0,%1,%2,%3}, [%4];" \
        : "=r"(r0), "=r"(r1), "=r"(r2), "=r"(r3) : "r"(addr))
#define LDMX2(r0, r1, addr) \
    asm volatile("ldmatrix.sync.aligned.m8n8.x2.shared.b16 {%0,%1}, [%2];" \
        : "=r"(r0), "=r"(r1) : "r"(addr))
#define MMA16816F16(c, a, b) \
    asm volatile("mma.sync.aligned.m16n8k16.row.col.f32.f16.f16.f32 " \
        "{%0,%1,%2,%3},{%4,%5,%6,%7},{%8,%9},{%0,%1,%2,%3};" \
        : "+f"((c)[0]), "+f"((c)[1]), "+f"((c)[2]), "+f"((c)[3]) \
        : "r"((a)[0]), "r"((a)[1]), "r"((a)[2]), "r"((a)[3]), "r"((b)[0]), "r"((b)[1]))

__device__ __forceinline__ uint32_t swz(int row, int chunk) {
    return (uint32_t)(row * 256 + ((chunk ^ (row & 7)) << 4));
}

__device__ __forceinline__ float softplus_f(float x) {
    return fmaxf(x, 0.f) + log1pf(expf(-fabsf(x)));
}
__device__ __forceinline__ float tanh_fast(float x) {
    float t;
    asm("tanh.approx.f32 %0, %1;" : "=f"(t) : "f"(x));
    return t;
}
__device__ __forceinline__ int mask_at(const void* m, int idx, int mode) {
    if (mode == 2) return ((const unsigned char*)m)[idx] != 0;
    if (mode == 1) return ((const float*)m)[idx] != 0.f;
    return ((const int*)m)[idx] != 0;
}

// ===================== P = pos @ Wp (SMEM-staged) + mask-dtype detection =====================
constexpr int SMEM_K0 = (Dc * Hc + 8 * Dc) * 4;  // 69632 B

__global__ void __launch_bounds__(1024, 1)
k0_P(const float* __restrict__ pos, const float* __restrict__ Wp,
     const uint4* __restrict__ mraw) {
    extern __shared__ float sm0[];
    float* sWp  = sm0;             // [Dc*Hc]
    float* sPos = sm0 + Dc * Hc;   // [8*Dc]
    const int tid = threadIdx.x;

    const int i = blockIdx.x * 1024 + tid;
    if (i < (Bc * Sc) / 16) {
        uint4 v = mraw[i];
        int fl = 0;
        uint32_t ws[4] = {v.x, v.y, v.z, v.w};
#pragma unroll
        for (int j = 0; j < 4; j++) {
            if (ws[j] == 0x3F800000u) fl |= 2;
            else if (ws[j] > 1u) fl |= 1;
        }
        if (fl) atomicOr(&g_flags, fl);
    }

    const float4* w4 = (const float4*)Wp;
    float4* sW4 = (float4*)sWp;
#pragma unroll
    for (int j = 0; j < 4; j++) sW4[tid + j * 1024] = w4[tid + j * 1024];
    const int rbase = blockIdx.x * 8;
    if (tid < 256) {
        const int r = tid >> 5, c = tid & 31;
        ((float4*)sPos)[tid] = ((const float4*)(pos + (size_t)(rbase + r) * Dc))[c];
    }
    __syncthreads();

    const int lr = tid >> 7, h = tid & 127;
    const float* pr = sPos + lr * Dc;
    float a0 = 0.f, a1 = 0.f, a2 = 0.f, a3 = 0.f;
#pragma unroll 8
    for (int d = 0; d < Dc; d += 4) {
        a0 = fmaf(pr[d + 0], sWp[(d + 0) * Hc + h], a0);
        a1 = fmaf(pr[d + 1], sWp[(d + 1) * Hc + h], a1);
        a2 = fmaf(pr[d + 2], sWp[(d + 2) * Hc + h], a2);
        a3 = fmaf(pr[d + 3], sWp[(d + 3) * Hc + h], a3);
    }
    g_P[(rbase + lr) * Hc + h] = (a0 + a1) + (a2 + a3);
}

// ===================== mma.sync score kernel (fp16 2-pass split) =====================
constexpr int OFF_AHI = 0;
constexpr int OFF_ALO = 32768;
constexpr int OFF_RED = 65536;                  // 128*9*4 = 4608
constexpr int SMEM_K1 = OFF_RED + 128 * 9 * 4;  // 70144

// fp32 -> fp16 hi/lo split: x = hi + lo exactly to fp16 rounding of the residual
__device__ __forceinline__ void split4h(float4 v, uint2& hh, uint2& ll) {
    __half2 h0 = __floats2half2_rn(v.x, v.y);
    __half2 h1 = __floats2half2_rn(v.z, v.w);
    float2 f0 = __half22float2(h0);
    float2 f1 = __half22float2(h1);
    __half2 l0 = __floats2half2_rn(v.x - f0.x, v.y - f0.y);
    __half2 l1 = __floats2half2_rn(v.z - f1.x, v.w - f1.y);
    hh.x = *(uint32_t*)&h0;
    hh.y = *(uint32_t*)&h1;
    ll.x = *(uint32_t*)&l0;
    ll.y = *(uint32_t*)&l1;
}

__global__ void __launch_bounds__(256, 1)
k1_mma(const float* __restrict__ X, const float* __restrict__ We, const float* __restrict__ z) {
    extern __shared__ char smc[];
    const uint32_t smb = smem_u32(smc);
    float* red = (float*)(smc + OFF_RED);
    const int tid = threadIdx.x;
    const int wid = tid >> 5, l = tid & 31;
    const int bn = wid * 16;

    // ---- stage WeT as fp16 (single version), load B fragments ----
    for (int i = tid; i < Dc * Hc; i += 256) {
        int d = i >> 7, h = i & 127;
        __half hv = __float2half_rn(We[i]);
        uint32_t a = swz(h, d >> 3) + (uint32_t)((d & 7) * 2);
        *(__half*)(smc + OFF_AHI + a) = hv;
    }
    __syncthreads();

    uint32_t Bh[8][2][2];
    {
        const int brow = bn + (l & 7);
        const int bc = (l >> 3) & 1;
#pragma unroll
        for (int ks = 0; ks < 8; ks++) {
#pragma unroll
            for (int j = 0; j < 2; j++) {
                uint32_t a = swz(brow + j * 8, 2 * ks + bc);
                LDMX2(Bh[ks][j][0], Bh[ks][j][1], smb + OFF_AHI + a);
            }
        }
    }
    const int c0 = bn + (l & 3) * 2;
    const float zv0 = __ldg(&z[c0]),     zv1 = __ldg(&z[c0 + 1]);
    const float zv2 = __ldg(&z[c0 + 8]), zv3 = __ldg(&z[c0 + 9]);
    __syncthreads();

    const int arow_off = (l & 7) + ((l >> 3) & 1) * 8;
    const int achk_off = (l >> 4) & 1;

    const int GD = gridDim.x;
    int t = blockIdx.x;
    float4 pf[16];
    if (t < TILES) {
        const float4* Xg = (const float4*)(X + (size_t)t * (128 * 128));
#pragma unroll
        for (int jj = 0; jj < 16; jj++) pf[jj] = Xg[tid + jj * 256];
    }

    for (; t < TILES; t += GD) {
        // ---- convert + store prefetched tile (fp16 hi/lo) ----
#pragma unroll
        for (int jj = 0; jj < 16; jj++) {
            int i4 = tid + jj * 256;
            int elem = i4 * 4;
            int row = elem >> 7, col = elem & 127;
            uint32_t a = swz(row, col >> 3) + (uint32_t)((col & 7) * 2);
            uint2 hh, ll;
            split4h(pf[jj], hh, ll);
            *(uint2*)(smc + OFF_AHI + a) = hh;
            *(uint2*)(smc + OFF_ALO + a) = ll;
        }
        __syncthreads();

        // ---- prefetch next tile (hidden behind GEMM) ----
        const int tn = t + GD;
        if (tn < TILES) {
            const float4* Xg = (const float4*)(X + (size_t)tn * (128 * 128));
#pragma unroll
            for (int jj = 0; jj < 16; jj++) pf[jj] = Xg[tid + jj * 256];
        }

        // ---- GEMM: C = Xhi*W + Xlo*W  (W = fp16(We)) ----
        float C[8][2][4];
#pragma unroll
        for (int f = 0; f < 8; f++)
#pragma unroll
            for (int j = 0; j < 2; j++)
#pragma unroll
                for (int q = 0; q < 4; q++) C[f][j][q] = 0.f;

#pragma unroll
        for (int ks = 0; ks < 8; ks++) {
            uint32_t A[8][4];
#pragma unroll
            for (int f = 0; f < 8; f++) {
                uint32_t a = swz(f * 16 + arow_off, 2 * ks + achk_off);
                LDMX4(A[f][0], A[f][1], A[f][2], A[f][3], smb + OFF_AHI + a);
            }
#pragma unroll
            for (int f = 0; f < 8; f++) {
                MMA16816F16(C[f][0], A[f], Bh[ks][0]);
                MMA16816F16(C[f][1], A[f], Bh[ks][1]);
            }
#pragma unroll
            for (int f = 0; f < 8; f++) {
                uint32_t a = swz(f * 16 + arow_off, 2 * ks + achk_off);
                LDMX4(A[f][0], A[f][1], A[f][2], A[f][3], smb + OFF_ALO + a);
            }
#pragma unroll
            for (int f = 0; f < 8; f++) {
                MMA16816F16(C[f][0], A[f], Bh[ks][0]);
                MMA16816F16(C[f][1], A[f], Bh[ks][1]);
            }
        }

        // ---- epilogue: partial z . tanh(C + P) per warp slice ----
        const int mb = t * 128;
#pragma unroll
        for (int f = 0; f < 8; f++) {
            const int r0 = f * 16 + (l >> 2), r1 = r0 + 8;
            const int s0 = (mb + r0) % Sc, s1 = (mb + r1) % Sc;
            float2 p00 = __ldg((const float2*)&g_P[s0 * Hc + c0]);
            float2 p01 = __ldg((const float2*)&g_P[s0 * Hc + c0 + 8]);
            float2 p10 = __ldg((const float2*)&g_P[s1 * Hc + c0]);
            float2 p11 = __ldg((const float2*)&g_P[s1 * Hc + c0 + 8]);
            float p0 = zv0 * tanh_fast(C[f][0][0] + p00.x) + zv1 * tanh_fast(C[f][0][1] + p00.y)
                     + zv2 * tanh_fast(C[f][1][0] + p01.x) + zv3 * tanh_fast(C[f][1][1] + p01.y);
            float p1 = zv0 * tanh_fast(C[f][0][2] + p10.x) + zv1 * tanh_fast(C[f][0][3] + p10.y)
                     + zv2 * tanh_fast(C[f][1][2] + p11.x) + zv3 * tanh_fast(C[f][1][3] + p11.y);
            p0 += __shfl_xor_sync(0xffffffffu, p0, 1);
            p0 += __shfl_xor_sync(0xffffffffu, p0, 2);
            p1 += __shfl_xor_sync(0xffffffffu, p1, 1);
            p1 += __shfl_xor_sync(0xffffffffu, p1, 2);
            if ((l & 3) == 0) { red[r0 * 9 + wid] = p0; red[r1 * 9 + wid] = p1; }
        }
        __syncthreads();
        if (tid < 128) {
            float s = 0.f;
#pragma unroll
            for (int w = 0; w < 8; w++) s += red[tid * 9 + w];
            g_scores[mb + tid] = s;
        }
        __syncthreads();
    }
}

// ===================== per-batch finalize (aux fused via last-block) =====================
__global__ void k2_finalize(const float* __restrict__ X,
                            const void* __restrict__ mask,
                            const float* __restrict__ Xitem,
                            const float* __restrict__ origin,
                            float* __restrict__ out) {
    __shared__ float sh_attn[Sc];
    __shared__ __align__(16) float sh_outv[Dc];
    __shared__ __align__(16) float sh_ws[4 * Dc];
    __shared__ float sh_w[4];
    __shared__ float sh_red[16];
    __shared__ float sh_res[4];
    __shared__ int   sh_len;
    __shared__ int   sh_last;

    const int b = blockIdx.x, tid = threadIdx.x;
    const int w = tid >> 5, l = tid & 31;
    const int fl = g_flags;
    const int mode = (fl & 1) ? 2 : ((fl & 2) ? 1 : 0);

    int cnt = mask_at(mask, b * Sc + tid, mode);
    if (tid + 128 < Sc) cnt += mask_at(mask, b * Sc + tid + 128, mode);
#pragma unroll
    for (int o = 16; o; o >>= 1) cnt += __shfl_xor_sync(0xffffffffu, cnt, o);
    if (l == 0) sh_w[w] = (float)cnt;
    __syncthreads();
    if (tid == 0) sh_len = (int)(sh_w[0] + sh_w[1] + sh_w[2] + sh_w[3]);
    __syncthreads();
    const int len = sh_len;

    float sc0 = 0.f, sc1 = 0.f, m0 = -FLT_MAX;
    if (tid < len)       { sc0 = g_scores[b * Sc + tid];       m0 = sc0; }
    if (tid + 128 < len) { sc1 = g_scores[b * Sc + tid + 128]; m0 = fmaxf(m0, sc1); }
#pragma unroll
    for (int o = 16; o; o >>= 1) m0 = fmaxf(m0, __shfl_xor_sync(0xffffffffu, m0, o));
    __syncthreads();
    if (l == 0) sh_w[w] = m0;
    __syncthreads();
    const float mx = fmaxf(fmaxf(sh_w[0], sh_w[1]), fmaxf(sh_w[2], sh_w[3]));

    float e0 = (tid < len) ? expf(sc0 - mx) : 0.f;
    float e1 = (tid + 128 < len) ? expf(sc1 - mx) : 0.f;
    float ss = e0 + e1;
#pragma unroll
    for (int o = 16; o; o >>= 1) ss += __shfl_xor_sync(0xffffffffu, ss, o);
    __syncthreads();
    if (l == 0) sh_w[w] = ss;
    __syncthreads();
    const float inv = 1.f / (sh_w[0] + sh_w[1] + sh_w[2] + sh_w[3]);
    sh_attn[tid] = e0 * inv;
    if (tid + 128 < Sc) sh_attn[tid + 128] = e1 * inv;
    __syncthreads();

    // ---- weighted sum: warp w -> rows = w (mod 4), lane l -> d = 4l..4l+3 ----
    const float4* Xb4 = (const float4*)(X + (size_t)b * Sc * Dc) + l;
    float4 acc0 = make_float4(0.f, 0.f, 0.f, 0.f);
    float4 acc1 = make_float4(0.f, 0.f, 0.f, 0.f);
    int r = w;
    for (; r + 4 < len; r += 8) {
        const float aw0 = sh_attn[r], aw1 = sh_attn[r + 4];
        const float4 x0 = __ldg(&Xb4[(size_t)r * 32]);
        const float4 x1 = __ldg(&Xb4[(size_t)(r + 4) * 32]);
        acc0.x = fmaf(aw0, x0.x, acc0.x); acc0.y = fmaf(aw0, x0.y, acc0.y);
        acc0.z = fmaf(aw0, x0.z, acc0.z); acc0.w = fmaf(aw0, x0.w, acc0.w);
        acc1.x = fmaf(aw1, x1.x, acc1.x); acc1.y = fmaf(aw1, x1.y, acc1.y);
        acc1.z = fmaf(aw1, x1.z, acc1.z); acc1.w = fmaf(aw1, x1.w, acc1.w);
    }
    if (r < len) {
        const float aw = sh_attn[r];
        const float4 x0 = __ldg(&Xb4[(size_t)r * 32]);
        acc0.x = fmaf(aw, x0.x, acc0.x); acc0.y = fmaf(aw, x0.y, acc0.y);
        acc0.z = fmaf(aw, x0.z, acc0.z); acc0.w = fmaf(aw, x0.w, acc0.w);
    }
    acc0.x += acc1.x; acc0.y += acc1.y; acc0.z += acc1.z; acc0.w += acc1.w;
    *(float4*)&sh_ws[w * Dc + 4 * l] = acc0;
    __syncthreads();
    const float ao = sh_ws[tid] + sh_ws[Dc + tid] + sh_ws[2 * Dc + tid] + sh_ws[3 * Dc + tid];

    const float lastv = sh_attn[len - 1] * __ldg(&X[(size_t)b * Sc * Dc + (size_t)(len - 1) * Dc + tid]);
    const float outv = ao - lastv;
    sh_outv[tid] = outv;

    const float xi = __ldg(&Xitem[b * Dc + tid]);
    float r0 = lastv * lastv, r1 = outv * outv, r2 = lastv * outv, r3 = ao * xi;
#pragma unroll
    for (int o = 16; o; o >>= 1) {
        r0 += __shfl_xor_sync(0xffffffffu, r0, o);
        r1 += __shfl_xor_sync(0xffffffffu, r1, o);
        r2 += __shfl_xor_sync(0xffffffffu, r2, o);
        r3 += __shfl_xor_sync(0xffffffffu, r3, o);
    }
    if (l == 0) { sh_red[w] = r0; sh_red[4 + w] = r1; sh_red[8 + w] = r2; sh_red[12 + w] = r3; }
    __syncthreads();
    if (tid < 4)
        sh_res[tid] = sh_red[tid * 4] + sh_red[tid * 4 + 1] + sh_red[tid * 4 + 2] + sh_red[tid * 4 + 3];
    __syncthreads();

    const float normOut = sqrtf(fmaxf(sh_res[1], 1e-12f));

    out[b * (Dc + 1) + tid] = ao;
    if (tid == 0) {
        out[b * (Dc + 1) + Dc] = sh_res[3];
        const float cosp = sh_res[2] / (sqrtf(fmaxf(sh_res[0], 1e-12f)) * normOut);
        const float pl = (1.f - cosp) * 0.5f;
        g_posloss[b] = softplus_f(-pl);
    }

    const float o0 = sh_outv[4 * l], o1 = sh_outv[4 * l + 1];
    const float o2 = sh_outv[4 * l + 2], o3 = sh_outv[4 * l + 3];
    const float4* Ob = (const float4*)(origin + (size_t)b * Nc * Dc);
    float nloss = 0.f;
    for (int n = w; n < Nc; n += 4) {
        const float4 og = Ob[n * 32 + l];
        float dot = og.x * o0 + og.y * o1 + og.z * o2 + og.w * o3;
        float nn = og.x * og.x + og.y * og.y + og.z * og.z + og.w * og.w;
#pragma unroll
        for (int o = 16; o; o >>= 1) {
            dot += __shfl_xor_sync(0xffffffffu, dot, o);
            nn  += __shfl_xor_sync(0xffffffffu, nn, o);
        }
        const float cosn = dot / (sqrtf(fmaxf(nn, 1e-12f)) * normOut);
        nloss += softplus_f((1.f - cosn) * 0.5f);
    }
    __syncthreads();
    if (l == 0) sh_w[w] = nloss;
    __syncthreads();
    if (tid == 0) g_negsum[b] = sh_w[0] + sh_w[1] + sh_w[2] + sh_w[3];

    // ---- last-block aux finalization ----
    __threadfence();
    __syncthreads();
    if (tid == 0) sh_last = (atomicAdd(&g_done, 1) == Bc - 1);
    __syncthreads();
    if (sh_last) {
        __threadfence();
        float v = 0.f;
#pragma unroll
        for (int j = 0; j < 8; j++) v += g_posloss[tid + j * 128];
#pragma unroll
        for (int o = 16; o; o >>= 1) v += __shfl_xor_sync(0xffffffffu, v, o);
        if (l == 0) sh_w[w] = v;
        __syncthreads();
        const float tot = sh_w[0] + sh_w[1] + sh_w[2] + sh_w[3];
#pragma unroll
        for (int j = 0; j < 8; j++) {
            const int bb = tid + j * 128;
            out[OUT_CONCAT + bb] = tot + g_negsum[bb];
        }
        if (tid == 0) { g_done = 0; g_flags = 0; }
    }
}

extern "C" void kernel_launch(void* const* d_in, const int* in_sizes, int n_in,
                              void* d_out, int out_size) {
    const float* X      = (const float*)d_in[0];
    const float* pos    = (const float*)d_in[1];
    const float* Xitem  = (const float*)d_in[2];
    const void*  mask   = d_in[3];
    const float* origin = (const float*)d_in[4];
    const float* Wp     = (const float*)d_in[5];
    const float* We     = (const float*)d_in[6];
    const float* z      = (const float*)d_in[7];
    float* out = (float*)d_out;

    cudaFuncSetAttribute(k0_P,   cudaFuncAttributeMaxDynamicSharedMemorySize, SMEM_K0);
    cudaFuncSetAttribute(k1_mma, cudaFuncAttributeMaxDynamicSharedMemorySize, SMEM_K1);

    k0_P<<<Sc / 8, 1024, SMEM_K0>>>(pos, Wp, (const uint4*)mask);
    k1_mma<<<148, 256, SMEM_K1>>>(X, We, z);
    k2_finalize<<<Bc, Dc>>>(X, mask, Xitem, origin, out);
}

// round 13
// speedup vs baseline: 1.6183x; 1.0610x over previous
#include <cuda_runtime.h>
#include <cuda_bf16.h>
#include <cuda_fp16.h>
#include <float.h>
#include <math.h>
#include <cstdint>

// Problem constants
constexpr int Bc = 1024;
constexpr int Sc = 200;
constexpr int Dc = 128;
constexpr int Hc = 128;
constexpr int Nc = 64;
constexpr int ROWS = Bc * Sc;             // 204800
constexpr int TILES = ROWS / 128;         // 1600
constexpr int OUT_CONCAT = Bc * (Dc + 1); // 132096

// Scratch
__device__ float g_P[Sc * Hc];
__device__ float g_scores[ROWS];
__device__ float g_posloss[Bc];
__device__ float g_negsum[Bc];
__device__ int   g_flags = 0;   // bit0 = bad (uint8), bit1 = f32
__device__ int   g_done  = 0;   // k2 completion counter

__device__ __forceinline__ uint32_t smem_u32(const void* p) {
    uint32_t a;
    asm("{ .reg .u64 t; cvta.to.shared.u64 t, %1; cvt.u32.u64 %0, t; }" : "=r"(a) : "l"(p));
    return a;
}

#define LDMX4(r0, r1, r2, r3, addr) \
    asm volatile("ldmatrix.sync.aligned.m8n8.x4.shared.b16 {%0,%1,%2,%3}, [%4];" \
        : "=r"(r0), "=r"(r1), "=r"(r2), "=r"(r3) : "r"(addr))
#define LDMX2(r0, r1, addr) \
    asm volatile("ldmatrix.sync.aligned.m8n8.x2.shared.b16 {%0,%1}, [%2];" \
        : "=r"(r0), "=r"(r1) : "r"(addr))
#define MMA16816F16(c, a, b) \
    asm volatile("mma.sync.aligned.m16n8k16.row.col.f32.f16.f16.f32 " \
        "{%0,%1,%2,%3},{%4,%5,%6,%7},{%8,%9},{%0,%1,%2,%3};" \
        : "+f"((c)[0]), "+f"((c)[1]), "+f"((c)[2]), "+f"((c)[3]) \
        : "r"((a)[0]), "r"((a)[1]), "r"((a)[2]), "r"((a)[3]), "r"((b)[0]), "r"((b)[1]))

__device__ __forceinline__ uint32_t swz(int row, int chunk) {
    return (uint32_t)(row * 256 + ((chunk ^ (row & 7)) << 4));
}

__device__ __forceinline__ float softplus_f(float x) {
    return fmaxf(x, 0.f) + log1pf(expf(-fabsf(x)));
}
__device__ __forceinline__ float tanh_fast(float x) {
    float t;
    asm("tanh.approx.f32 %0, %1;" : "=f"(t) : "f"(x));
    return t;
}
__device__ __forceinline__ int mask_at(const void* m, int idx, int mode) {
    if (mode == 2) return ((const unsigned char*)m)[idx] != 0;
    if (mode == 1) return ((const float*)m)[idx] != 0.f;
    return ((const int*)m)[idx] != 0;
}

// ===================== P = pos @ Wp (SMEM-staged) + mask-dtype detection =====================
constexpr int SMEM_K0 = (Dc * Hc + 8 * Dc) * 4;  // 69632 B

__global__ void __launch_bounds__(1024, 1)
k0_P(const float* __restrict__ pos, const float* __restrict__ Wp,
     const uint4* __restrict__ mraw) {
    extern __shared__ float sm0[];
    float* sWp  = sm0;             // [Dc*Hc]
    float* sPos = sm0 + Dc * Hc;   // [8*Dc]
    const int tid = threadIdx.x;

    const int i = blockIdx.x * 1024 + tid;
    if (i < (Bc * Sc) / 16) {
        uint4 v = mraw[i];
        int fl = 0;
        uint32_t ws[4] = {v.x, v.y, v.z, v.w};
#pragma unroll
        for (int j = 0; j < 4; j++) {
            if (ws[j] == 0x3F800000u) fl |= 2;
            else if (ws[j] > 1u) fl |= 1;
        }
        if (fl) atomicOr(&g_flags, fl);
    }

    const float4* w4 = (const float4*)Wp;
    float4* sW4 = (float4*)sWp;
#pragma unroll
    for (int j = 0; j < 4; j++) sW4[tid + j * 1024] = w4[tid + j * 1024];
    const int rbase = blockIdx.x * 8;
    if (tid < 256) {
        const int r = tid >> 5, c = tid & 31;
        ((float4*)sPos)[tid] = ((const float4*)(pos + (size_t)(rbase + r) * Dc))[c];
    }
    __syncthreads();

    const int lr = tid >> 7, h = tid & 127;
    const float* pr = sPos + lr * Dc;
    float a0 = 0.f, a1 = 0.f, a2 = 0.f, a3 = 0.f;
#pragma unroll 8
    for (int d = 0; d < Dc; d += 4) {
        a0 = fmaf(pr[d + 0], sWp[(d + 0) * Hc + h], a0);
        a1 = fmaf(pr[d + 1], sWp[(d + 1) * Hc + h], a1);
        a2 = fmaf(pr[d + 2], sWp[(d + 2) * Hc + h], a2);
        a3 = fmaf(pr[d + 3], sWp[(d + 3) * Hc + h], a3);
    }
    g_P[(rbase + lr) * Hc + h] = (a0 + a1) + (a2 + a3);
}

// ===================== mma.sync score kernel (single-pass fp16) =====================
constexpr int OFF_A   = 0;                      // 32768 B tile (fp16)
constexpr int OFF_RED = 32768;                  // 128*9*4 = 4608
constexpr int SMEM_K1 = OFF_RED + 128 * 9 * 4;  // 37376

__device__ __forceinline__ void cvt4h(float4 v, uint2& hh) {
    __half2 h0 = __floats2half2_rn(v.x, v.y);
    __half2 h1 = __floats2half2_rn(v.z, v.w);
    hh.x = *(uint32_t*)&h0;
    hh.y = *(uint32_t*)&h1;
}

__global__ void __launch_bounds__(256, 1)
k1_mma(const float* __restrict__ X, const float* __restrict__ We, const float* __restrict__ z) {
    extern __shared__ char smc[];
    const uint32_t smb = smem_u32(smc);
    float* red = (float*)(smc + OFF_RED);
    const int tid = threadIdx.x;
    const int wid = tid >> 5, l = tid & 31;
    const int bn = wid * 16;

    // ---- stage WeT as fp16 in the A buffer, load B fragments ----
    for (int i = tid; i < Dc * Hc; i += 256) {
        int d = i >> 7, h = i & 127;
        __half hv = __float2half_rn(We[i]);
        uint32_t a = swz(h, d >> 3) + (uint32_t)((d & 7) * 2);
        *(__half*)(smc + OFF_A + a) = hv;
    }
    __syncthreads();

    uint32_t Bh[8][2][2];
    {
        const int brow = bn + (l & 7);
        const int bc = (l >> 3) & 1;
#pragma unroll
        for (int ks = 0; ks < 8; ks++) {
#pragma unroll
            for (int j = 0; j < 2; j++) {
                uint32_t a = swz(brow + j * 8, 2 * ks + bc);
                LDMX2(Bh[ks][j][0], Bh[ks][j][1], smb + OFF_A + a);
            }
        }
    }
    const int c0 = bn + (l & 3) * 2;
    const float zv0 = __ldg(&z[c0]),     zv1 = __ldg(&z[c0 + 1]);
    const float zv2 = __ldg(&z[c0 + 8]), zv3 = __ldg(&z[c0 + 9]);
    __syncthreads();

    const int arow_off = (l & 7) + ((l >> 3) & 1) * 8;
    const int achk_off = (l >> 4) & 1;

    const int GD = gridDim.x;
    int t = blockIdx.x;
    float4 pf[16];
    if (t < TILES) {
        const float4* Xg = (const float4*)(X + (size_t)t * (128 * 128));
#pragma unroll
        for (int jj = 0; jj < 16; jj++) pf[jj] = Xg[tid + jj * 256];
    }

    for (; t < TILES; t += GD) {
        // ---- convert + store prefetched tile (fp16) ----
#pragma unroll
        for (int jj = 0; jj < 16; jj++) {
            int i4 = tid + jj * 256;
            int elem = i4 * 4;
            int row = elem >> 7, col = elem & 127;
            uint32_t a = swz(row, col >> 3) + (uint32_t)((col & 7) * 2);
            uint2 hh;
            cvt4h(pf[jj], hh);
            *(uint2*)(smc + OFF_A + a) = hh;
        }
        __syncthreads();

        // ---- prefetch next tile (hidden behind GEMM) ----
        const int tn = t + GD;
        if (tn < TILES) {
            const float4* Xg = (const float4*)(X + (size_t)tn * (128 * 128));
#pragma unroll
            for (int jj = 0; jj < 16; jj++) pf[jj] = Xg[tid + jj * 256];
        }

        // ---- GEMM: C = fp16(X) * fp16(We) ----
        float C[8][2][4];
#pragma unroll
        for (int f = 0; f < 8; f++)
#pragma unroll
            for (int j = 0; j < 2; j++)
#pragma unroll
                for (int q = 0; q < 4; q++) C[f][j][q] = 0.f;

#pragma unroll
        for (int ks = 0; ks < 8; ks++) {
            uint32_t A[8][4];
#pragma unroll
            for (int f = 0; f < 8; f++) {
                uint32_t a = swz(f * 16 + arow_off, 2 * ks + achk_off);
                LDMX4(A[f][0], A[f][1], A[f][2], A[f][3], smb + OFF_A + a);
            }
#pragma unroll
            for (int f = 0; f < 8; f++) {
                MMA16816F16(C[f][0], A[f], Bh[ks][0]);
                MMA16816F16(C[f][1], A[f], Bh[ks][1]);
            }
        }

        // ---- epilogue: partial z . tanh(C + P) per warp slice ----
        const int mb = t * 128;
#pragma unroll
        for (int f = 0; f < 8; f++) {
            const int r0 = f * 16 + (l >> 2), r1 = r0 + 8;
            const int s0 = (mb + r0) % Sc, s1 = (mb + r1) % Sc;
            float2 p00 = __ldg((const float2*)&g_P[s0 * Hc + c0]);
            float2 p01 = __ldg((const float2*)&g_P[s0 * Hc + c0 + 8]);
            float2 p10 = __ldg((const float2*)&g_P[s1 * Hc + c0]);
            float2 p11 = __ldg((const float2*)&g_P[s1 * Hc + c0 + 8]);
            float p0 = zv0 * tanh_fast(C[f][0][0] + p00.x) + zv1 * tanh_fast(C[f][0][1] + p00.y)
                     + zv2 * tanh_fast(C[f][1][0] + p01.x) + zv3 * tanh_fast(C[f][1][1] + p01.y);
            float p1 = zv0 * tanh_fast(C[f][0][2] + p10.x) + zv1 * tanh_fast(C[f][0][3] + p10.y)
                     + zv2 * tanh_fast(C[f][1][2] + p11.x) + zv3 * tanh_fast(C[f][1][3] + p11.y);
            p0 += __shfl_xor_sync(0xffffffffu, p0, 1);
            p0 += __shfl_xor_sync(0xffffffffu, p0, 2);
            p1 += __shfl_xor_sync(0xffffffffu, p1, 1);
            p1 += __shfl_xor_sync(0xffffffffu, p1, 2);
            if ((l & 3) == 0) { red[r0 * 9 + wid] = p0; red[r1 * 9 + wid] = p1; }
        }
        __syncthreads();
        if (tid < 128) {
            float s = 0.f;
#pragma unroll
            for (int w = 0; w < 8; w++) s += red[tid * 9 + w];
            g_scores[mb + tid] = s;
        }
        __syncthreads();
    }
}

// ===================== per-batch finalize (aux fused via last-block) =====================
__global__ void k2_finalize(const float* __restrict__ X,
                            const void* __restrict__ mask,
                            const float* __restrict__ Xitem,
                            const float* __restrict__ origin,
                            float* __restrict__ out) {
    __shared__ float sh_attn[Sc];
    __shared__ __align__(16) float sh_outv[Dc];
    __shared__ __align__(16) float sh_ws[4 * Dc];
    __shared__ float sh_w[4];
    __shared__ float sh_red[16];
    __shared__ float sh_res[4];
    __shared__ int   sh_len;
    __shared__ int   sh_last;

    const int b = blockIdx.x, tid = threadIdx.x;
    const int w = tid >> 5, l = tid & 31;
    const int fl = g_flags;
    const int mode = (fl & 1) ? 2 : ((fl & 2) ? 1 : 0);

    int cnt = mask_at(mask, b * Sc + tid, mode);
    if (tid + 128 < Sc) cnt += mask_at(mask, b * Sc + tid + 128, mode);
#pragma unroll
    for (int o = 16; o; o >>= 1) cnt += __shfl_xor_sync(0xffffffffu, cnt, o);
    if (l == 0) sh_w[w] = (float)cnt;
    __syncthreads();
    if (tid == 0) sh_len = (int)(sh_w[0] + sh_w[1] + sh_w[2] + sh_w[3]);
    __syncthreads();
    const int len = sh_len;

    float sc0 = 0.f, sc1 = 0.f, m0 = -FLT_MAX;
    if (tid < len)       { sc0 = g_scores[b * Sc + tid];       m0 = sc0; }
    if (tid + 128 < len) { sc1 = g_scores[b * Sc + tid + 128]; m0 = fmaxf(m0, sc1); }
#pragma unroll
    for (int o = 16; o; o >>= 1) m0 = fmaxf(m0, __shfl_xor_sync(0xffffffffu, m0, o));
    __syncthreads();
    if (l == 0) sh_w[w] = m0;
    __syncthreads();
    const float mx = fmaxf(fmaxf(sh_w[0], sh_w[1]), fmaxf(sh_w[2], sh_w[3]));

    float e0 = (tid < len) ? expf(sc0 - mx) : 0.f;
    float e1 = (tid + 128 < len) ? expf(sc1 - mx) : 0.f;
    float ss = e0 + e1;
#pragma unroll
    for (int o = 16; o; o >>= 1) ss += __shfl_xor_sync(0xffffffffu, ss, o);
    __syncthreads();
    if (l == 0) sh_w[w] = ss;
    __syncthreads();
    const float inv = 1.f / (sh_w[0] + sh_w[1] + sh_w[2] + sh_w[3]);
    sh_attn[tid] = e0 * inv;
    if (tid + 128 < Sc) sh_attn[tid + 128] = e1 * inv;
    __syncthreads();

    // ---- weighted sum: warp w -> rows = w (mod 4), lane l -> d = 4l..4l+3 ----
    const float4* Xb4 = (const float4*)(X + (size_t)b * Sc * Dc) + l;
    float4 acc0 = make_float4(0.f, 0.f, 0.f, 0.f);
    float4 acc1 = make_float4(0.f, 0.f, 0.f, 0.f);
    int r = w;
    for (; r + 4 < len; r += 8) {
        const float aw0 = sh_attn[r], aw1 = sh_attn[r + 4];
        const float4 x0 = __ldg(&Xb4[(size_t)r * 32]);
        const float4 x1 = __ldg(&Xb4[(size_t)(r + 4) * 32]);
        acc0.x = fmaf(aw0, x0.x, acc0.x); acc0.y = fmaf(aw0, x0.y, acc0.y);
        acc0.z = fmaf(aw0, x0.z, acc0.z); acc0.w = fmaf(aw0, x0.w, acc0.w);
        acc1.x = fmaf(aw1, x1.x, acc1.x); acc1.y = fmaf(aw1, x1.y, acc1.y);
        acc1.z = fmaf(aw1, x1.z, acc1.z); acc1.w = fmaf(aw1, x1.w, acc1.w);
    }
    if (r < len) {
        const float aw = sh_attn[r];
        const float4 x0 = __ldg(&Xb4[(size_t)r * 32]);
        acc0.x = fmaf(aw, x0.x, acc0.x); acc0.y = fmaf(aw, x0.y, acc0.y);
        acc0.z = fmaf(aw, x0.z, acc0.z); acc0.w = fmaf(aw, x0.w, acc0.w);
    }
    acc0.x += acc1.x; acc0.y += acc1.y; acc0.z += acc1.z; acc0.w += acc1.w;
    *(float4*)&sh_ws[w * Dc + 4 * l] = acc0;
    __syncthreads();
    const float ao = sh_ws[tid] + sh_ws[Dc + tid] + sh_ws[2 * Dc + tid] + sh_ws[3 * Dc + tid];

    const float lastv = sh_attn[len - 1] * __ldg(&X[(size_t)b * Sc * Dc + (size_t)(len - 1) * Dc + tid]);
    const float outv = ao - lastv;
    sh_outv[tid] = outv;

    const float xi = __ldg(&Xitem[b * Dc + tid]);
    float r0 = lastv * lastv, r1 = outv * outv, r2 = lastv * outv, r3 = ao * xi;
#pragma unroll
    for (int o = 16; o; o >>= 1) {
        r0 += __shfl_xor_sync(0xffffffffu, r0, o);
        r1 += __shfl_xor_sync(0xffffffffu, r1, o);
        r2 += __shfl_xor_sync(0xffffffffu, r2, o);
        r3 += __shfl_xor_sync(0xffffffffu, r3, o);
    }
    if (l == 0) { sh_red[w] = r0; sh_red[4 + w] = r1; sh_red[8 + w] = r2; sh_red[12 + w] = r3; }
    __syncthreads();
    if (tid < 4)
        sh_res[tid] = sh_red[tid * 4] + sh_red[tid * 4 + 1] + sh_red[tid * 4 + 2] + sh_red[tid * 4 + 3];
    __syncthreads();

    const float normOut = sqrtf(fmaxf(sh_res[1], 1e-12f));

    out[b * (Dc + 1) + tid] = ao;
    if (tid == 0) {
        out[b * (Dc + 1) + Dc] = sh_res[3];
        const float cosp = sh_res[2] / (sqrtf(fmaxf(sh_res[0], 1e-12f)) * normOut);
        const float pl = (1.f - cosp) * 0.5f;
        g_posloss[b] = softplus_f(-pl);
    }

    const float o0 = sh_outv[4 * l], o1 = sh_outv[4 * l + 1];
    const float o2 = sh_outv[4 * l + 2], o3 = sh_outv[4 * l + 3];
    const float4* Ob = (const float4*)(origin + (size_t)b * Nc * Dc);
    float nloss = 0.f;
    for (int n = w; n < Nc; n += 4) {
        const float4 og = Ob[n * 32 + l];
        float dot = og.x * o0 + og.y * o1 + og.z * o2 + og.w * o3;
        float nn = og.x * og.x + og.y * og.y + og.z * og.z + og.w * og.w;
#pragma unroll
        for (int o = 16; o; o >>= 1) {
            dot += __shfl_xor_sync(0xffffffffu, dot, o);
            nn  += __shfl_xor_sync(0xffffffffu, nn, o);
        }
        const float cosn = dot / (sqrtf(fmaxf(nn, 1e-12f)) * normOut);
        nloss += softplus_f((1.f - cosn) * 0.5f);
    }
    __syncthreads();
    if (l == 0) sh_w[w] = nloss;
    __syncthreads();
    if (tid == 0) g_negsum[b] = sh_w[0] + sh_w[1] + sh_w[2] + sh_w[3];

    // ---- last-block aux finalization ----
    __threadfence();
    __syncthreads();
    if (tid == 0) sh_last = (atomicAdd(&g_done, 1) == Bc - 1);
    __syncthreads();
    if (sh_last) {
        __threadfence();
        float v = 0.f;
#pragma unroll
        for (int j = 0; j < 8; j++) v += g_posloss[tid + j * 128];
#pragma unroll
        for (int o = 16; o; o >>= 1) v += __shfl_xor_sync(0xffffffffu, v, o);
        if (l == 0) sh_w[w] = v;
        __syncthreads();
        const float tot = sh_w[0] + sh_w[1] + sh_w[2] + sh_w[3];
#pragma unroll
        for (int j = 0; j < 8; j++) {
            const int bb = tid + j * 128;
            out[OUT_CONCAT + bb] = tot + g_negsum[bb];
        }
        if (tid == 0) { g_done = 0; g_flags = 0; }
    }
}

extern "C" void kernel_launch(void* const* d_in, const int* in_sizes, int n_in,
                              void* d_out, int out_size) {
    const float* X      = (const float*)d_in[0];
    const float* pos    = (const float*)d_in[1];
    const float* Xitem  = (const float*)d_in[2];
    const void*  mask   = d_in[3];
    const float* origin = (const float*)d_in[4];
    const float* Wp     = (const float*)d_in[5];
    const float* We     = (const float*)d_in[6];
    const float* z      = (const float*)d_in[7];
    float* out = (float*)d_out;

    cudaFuncSetAttribute(k0_P,   cudaFuncAttributeMaxDynamicSharedMemorySize, SMEM_K0);
    cudaFuncSetAttribute(k1_mma, cudaFuncAttributeMaxDynamicSharedMemorySize, SMEM_K1);

    k0_P<<<Sc / 8, 1024, SMEM_K0>>>(pos, Wp, (const uint4*)mask);
    k1_mma<<<148, 256, SMEM_K1>>>(X, We, z);
    k2_finalize<<<Bc, Dc>>>(X, mask, Xitem, origin, out);
}

// round 15
// speedup vs baseline: 1.8516x; 1.1442x over previous
#include <cuda_runtime.h>
#include <cuda_bf16.h>
#include <cuda_fp16.h>
#include <float.h>
#include <math.h>
#include <cstdint>

// Problem constants
constexpr int Bc = 1024;
constexpr int Sc = 200;
constexpr int Dc = 128;
constexpr int Hc = 128;
constexpr int Nc = 64;
constexpr int ROWS = Bc * Sc;             // 204800
constexpr int TILES = ROWS / 128;         // 1600
constexpr int OUT_CONCAT = Bc * (Dc + 1); // 132096
constexpr int PCTAS = 100;                // CTAs computing P (2 rows each)

// Scratch
__device__ float g_P[Sc * Hc];
__device__ float g_scores[ROWS];
__device__ float g_posloss[Bc];
__device__ float g_negsum[Bc];
__device__ int   g_flags = 0;   // bit0 = bad (uint8), bit1 = f32
__device__ int   g_done  = 0;   // k2 completion counter
__device__ int   g_pdone = 0;   // P-phase completion counter

__device__ __forceinline__ uint32_t smem_u32(const void* p) {
    uint32_t a;
    asm("{ .reg .u64 t; cvta.to.shared.u64 t, %1; cvt.u32.u64 %0, t; }" : "=r"(a) : "l"(p));
    return a;
}

#define LDMX4(r0, r1, r2, r3, addr) \
    asm volatile("ldmatrix.sync.aligned.m8n8.x4.shared.b16 {%0,%1,%2,%3}, [%4];" \
        : "=r"(r0), "=r"(r1), "=r"(r2), "=r"(r3) : "r"(addr))
#define LDMX2(r0, r1, addr) \
    asm volatile("ldmatrix.sync.aligned.m8n8.x2.shared.b16 {%0,%1}, [%2];" \
        : "=r"(r0), "=r"(r1) : "r"(addr))
#define MMA16816F16(c, a, b) \
    asm volatile("mma.sync.aligned.m16n8k16.row.col.f32.f16.f16.f32 " \
        "{%0,%1,%2,%3},{%4,%5,%6,%7},{%8,%9},{%0,%1,%2,%3};" \
        : "+f"((c)[0]), "+f"((c)[1]), "+f"((c)[2]), "+f"((c)[3]) \
        : "r"((a)[0]), "r"((a)[1]), "r"((a)[2]), "r"((a)[3]), "r"((b)[0]), "r"((b)[1]))

__device__ __forceinline__ uint32_t swz(int row, int chunk) {
    return (uint32_t)(row * 256 + ((chunk ^ (row & 7)) << 4));
}

__device__ __forceinline__ float softplus_f(float x) {
    return fmaxf(x, 0.f) + log1pf(expf(-fabsf(x)));
}
__device__ __forceinline__ float tanh_fast(float x) {
    float t;
    asm("tanh.approx.f32 %0, %1;" : "=f"(t) : "f"(x));
    return t;
}
__device__ __forceinline__ int mask_at(const void* m, int idx, int mode) {
    if (mode == 2) return ((const unsigned char*)m)[idx] != 0;
    if (mode == 1) return ((const float*)m)[idx] != 0.f;
    return ((const int*)m)[idx] != 0;
}

// ===================== mma.sync score kernel (single-pass fp16, fused P prologue) =====================
constexpr int OFF_A   = 0;                      // 32768 B tile (fp16)
constexpr int OFF_RED = 32768;                  // 128*9*4 = 4608
constexpr int SMEM_K1 = OFF_RED + 128 * 9 * 4;  // 37376

__device__ __forceinline__ void cvt4h(float4 v, uint2& hh) {
    __half2 h0 = __floats2half2_rn(v.x, v.y);
    __half2 h1 = __floats2half2_rn(v.z, v.w);
    hh.x = *(uint32_t*)&h0;
    hh.y = *(uint32_t*)&h1;
}

__global__ void __launch_bounds__(256, 1)
k1_mma(const float* __restrict__ X, const float* __restrict__ We, const float* __restrict__ z,
       const float* __restrict__ pos, const float* __restrict__ Wp,
       const uint4* __restrict__ mraw) {
    extern __shared__ char smc[];
    const uint32_t smb = smem_u32(smc);
    float* red = (float*)(smc + OFF_RED);
    const int tid = threadIdx.x;
    const int wid = tid >> 5, l = tid & 31;
    const int bn = wid * 16;
    const int GD = gridDim.x;

    // ---- fire tile-0 LDGs first (DRAM latency covers the P phase) ----
    int t = blockIdx.x;
    float4 pf[16];
    if (t < TILES) {
        const float4* Xg = (const float4*)(X + (size_t)t * (128 * 128));
#pragma unroll
        for (int jj = 0; jj < 16; jj++) pf[jj] = Xg[tid + jj * 256];
    }

    // ---- mask dtype scan (12800 uint4 over 148 CTAs) ----
    {
        const int mi = blockIdx.x * 256 + tid;
        if (mi < (Bc * Sc) / 16) {
            uint4 v = mraw[mi];
            int fl = 0;
            uint32_t ws[4] = {v.x, v.y, v.z, v.w};
#pragma unroll
            for (int j = 0; j < 4; j++) {
                if (ws[j] == 0x3F800000u) fl |= 2;
                else if (ws[j] > 1u) fl |= 1;
            }
            if (fl) atomicOr(&g_flags, fl);
        }
    }

    // ---- P phase: CTAs 0..99 compute 2 rows each ----
    if (blockIdx.x < PCTAS) {
        const int lr = tid >> 7;             // 0 / 1
        const int h  = tid & 127;
        const int s  = blockIdx.x * 2 + lr;  // < 200
        const float* pr = pos + s * Dc;
        const float* wc = Wp + h;
        float a0 = 0.f, a1 = 0.f, a2 = 0.f, a3 = 0.f;
        float a4 = 0.f, a5 = 0.f, a6 = 0.f, a7 = 0.f;
#pragma unroll
        for (int d = 0; d < Dc; d += 8) {
            a0 = fmaf(__ldg(&pr[d + 0]), __ldg(&wc[(d + 0) * Hc]), a0);
            a1 = fmaf(__ldg(&pr[d + 1]), __ldg(&wc[(d + 1) * Hc]), a1);
            a2 = fmaf(__ldg(&pr[d + 2]), __ldg(&wc[(d + 2) * Hc]), a2);
            a3 = fmaf(__ldg(&pr[d + 3]), __ldg(&wc[(d + 3) * Hc]), a3);
            a4 = fmaf(__ldg(&pr[d + 4]), __ldg(&wc[(d + 4) * Hc]), a4);
            a5 = fmaf(__ldg(&pr[d + 5]), __ldg(&wc[(d + 5) * Hc]), a5);
            a6 = fmaf(__ldg(&pr[d + 6]), __ldg(&wc[(d + 6) * Hc]), a6);
            a7 = fmaf(__ldg(&pr[d + 7]), __ldg(&wc[(d + 7) * Hc]), a7);
        }
        g_P[s * Hc + h] = ((a0 + a1) + (a2 + a3)) + ((a4 + a5) + (a6 + a7));
        __syncthreads();
        if (tid == 0) { __threadfence(); atomicAdd(&g_pdone, 1); }
    }

    // ---- stage WeT as fp16 in the A buffer, load B fragments ----
    for (int i = tid; i < Dc * Hc; i += 256) {
        int d = i >> 7, h = i & 127;
        __half hv = __float2half_rn(We[i]);
        uint32_t a = swz(h, d >> 3) + (uint32_t)((d & 7) * 2);
        *(__half*)(smc + OFF_A + a) = hv;
    }
    __syncthreads();

    uint32_t Bh[8][2][2];
    {
        const int brow = bn + (l & 7);
        const int bc = (l >> 3) & 1;
#pragma unroll
        for (int ks = 0; ks < 8; ks++) {
#pragma unroll
            for (int j = 0; j < 2; j++) {
                uint32_t a = swz(brow + j * 8, 2 * ks + bc);
                LDMX2(Bh[ks][j][0], Bh[ks][j][1], smb + OFF_A + a);
            }
        }
    }
    const int c0 = bn + (l & 3) * 2;
    const float zv0 = __ldg(&z[c0]),     zv1 = __ldg(&z[c0 + 1]);
    const float zv2 = __ldg(&z[c0 + 8]), zv3 = __ldg(&z[c0 + 9]);
    __syncthreads();

    const int arow_off = (l & 7) + ((l >> 3) & 1) * 8;
    const int achk_off = (l >> 4) & 1;

    bool need_wait = true;
    for (; t < TILES; t += GD) {
        // ---- convert + store prefetched tile (fp16) ----
#pragma unroll
        for (int jj = 0; jj < 16; jj++) {
            int i4 = tid + jj * 256;
            int elem = i4 * 4;
            int row = elem >> 7, col = elem & 127;
            uint32_t a = swz(row, col >> 3) + (uint32_t)((col & 7) * 2);
            uint2 hh;
            cvt4h(pf[jj], hh);
            *(uint2*)(smc + OFF_A + a) = hh;
        }
        __syncthreads();

        // ---- prefetch next tile (hidden behind GEMM) ----
        const int tn = t + GD;
        if (tn < TILES) {
            const float4* Xg = (const float4*)(X + (size_t)tn * (128 * 128));
#pragma unroll
            for (int jj = 0; jj < 16; jj++) pf[jj] = Xg[tid + jj * 256];
        }

        // ---- GEMM: C = fp16(X) * fp16(We) ----
        float C[8][2][4];
#pragma unroll
        for (int f = 0; f < 8; f++)
#pragma unroll
            for (int j = 0; j < 2; j++)
#pragma unroll
                for (int q = 0; q < 4; q++) C[f][j][q] = 0.f;

#pragma unroll
        for (int ks = 0; ks < 8; ks++) {
            uint32_t A[8][4];
#pragma unroll
            for (int f = 0; f < 8; f++) {
                uint32_t a = swz(f * 16 + arow_off, 2 * ks + achk_off);
                LDMX4(A[f][0], A[f][1], A[f][2], A[f][3], smb + OFF_A + a);
            }
#pragma unroll
            for (int f = 0; f < 8; f++) {
                MMA16816F16(C[f][0], A[f], Bh[ks][0]);
                MMA16816F16(C[f][1], A[f], Bh[ks][1]);
            }
        }

        // ---- one-time wait: all P rows visible before first epilogue ----
        if (need_wait) {
            if (tid == 0) {
                while (*(volatile int*)&g_pdone < PCTAS) __nanosleep(32);
                __threadfence();
            }
            __syncthreads();
            need_wait = false;
        }

        // ---- epilogue: partial z . tanh(C + P) per warp slice ----
        const int mb = t * 128;
#pragma unroll
        for (int f = 0; f < 8; f++) {
            const int r0 = f * 16 + (l >> 2), r1 = r0 + 8;
            const int s0 = (mb + r0) % Sc, s1 = (mb + r1) % Sc;
            float2 p00 = __ldg((const float2*)&g_P[s0 * Hc + c0]);
            float2 p01 = __ldg((const float2*)&g_P[s0 * Hc + c0 + 8]);
            float2 p10 = __ldg((const float2*)&g_P[s1 * Hc + c0]);
            float2 p11 = __ldg((const float2*)&g_P[s1 * Hc + c0 + 8]);
            float p0 = zv0 * tanh_fast(C[f][0][0] + p00.x) + zv1 * tanh_fast(C[f][0][1] + p00.y)
                     + zv2 * tanh_fast(C[f][1][0] + p01.x) + zv3 * tanh_fast(C[f][1][1] + p01.y);
            float p1 = zv0 * tanh_fast(C[f][0][2] + p10.x) + zv1 * tanh_fast(C[f][0][3] + p10.y)
                     + zv2 * tanh_fast(C[f][1][2] + p11.x) + zv3 * tanh_fast(C[f][1][3] + p11.y);
            p0 += __shfl_xor_sync(0xffffffffu, p0, 1);
            p0 += __shfl_xor_sync(0xffffffffu, p0, 2);
            p1 += __shfl_xor_sync(0xffffffffu, p1, 1);
            p1 += __shfl_xor_sync(0xffffffffu, p1, 2);
            if ((l & 3) == 0) { red[r0 * 9 + wid] = p0; red[r1 * 9 + wid] = p1; }
        }
        __syncthreads();
        if (tid < 128) {
            float s = 0.f;
#pragma unroll
            for (int w = 0; w < 8; w++) s += red[tid * 9 + w];
            g_scores[mb + tid] = s;
        }
        // NOTE: no trailing sync — next iteration's convert-sync provides the ordering
    }
}

// ===================== per-batch finalize (aux fused via last-block) =====================
__global__ void k2_finalize(const float* __restrict__ X,
                            const void* __restrict__ mask,
                            const float* __restrict__ Xitem,
                            const float* __restrict__ origin,
                            float* __restrict__ out) {
    __shared__ float sh_attn[Sc];
    __shared__ __align__(16) float sh_outv[Dc];
    __shared__ __align__(16) float sh_ws[4 * Dc];
    __shared__ float sh_w[4];
    __shared__ float sh_red[16];
    __shared__ float sh_res[4];
    __shared__ int   sh_len;
    __shared__ int   sh_last;

    const int b = blockIdx.x, tid = threadIdx.x;
    const int w = tid >> 5, l = tid & 31;
    const int fl = g_flags;
    const int mode = (fl & 1) ? 2 : ((fl & 2) ? 1 : 0);

    int cnt = mask_at(mask, b * Sc + tid, mode);
    if (tid + 128 < Sc) cnt += mask_at(mask, b * Sc + tid + 128, mode);
#pragma unroll
    for (int o = 16; o; o >>= 1) cnt += __shfl_xor_sync(0xffffffffu, cnt, o);
    if (l == 0) sh_w[w] = (float)cnt;
    __syncthreads();
    if (tid == 0) sh_len = (int)(sh_w[0] + sh_w[1] + sh_w[2] + sh_w[3]);
    __syncthreads();
    const int len = sh_len;

    float sc0 = 0.f, sc1 = 0.f, m0 = -FLT_MAX;
    if (tid < len)       { sc0 = g_scores[b * Sc + tid];       m0 = sc0; }
    if (tid + 128 < len) { sc1 = g_scores[b * Sc + tid + 128]; m0 = fmaxf(m0, sc1); }
#pragma unroll
    for (int o = 16; o; o >>= 1) m0 = fmaxf(m0, __shfl_xor_sync(0xffffffffu, m0, o));
    __syncthreads();
    if (l == 0) sh_w[w] = m0;
    __syncthreads();
    const float mx = fmaxf(fmaxf(sh_w[0], sh_w[1]), fmaxf(sh_w[2], sh_w[3]));

    float e0 = (tid < len) ? expf(sc0 - mx) : 0.f;
    float e1 = (tid + 128 < len) ? expf(sc1 - mx) : 0.f;
    float ss = e0 + e1;
#pragma unroll
    for (int o = 16; o; o >>= 1) ss += __shfl_xor_sync(0xffffffffu, ss, o);
    __syncthreads();
    if (l == 0) sh_w[w] = ss;
    __syncthreads();
    const float inv = 1.f / (sh_w[0] + sh_w[1] + sh_w[2] + sh_w[3]);
    sh_attn[tid] = e0 * inv;
    if (tid + 128 < Sc) sh_attn[tid + 128] = e1 * inv;
    __syncthreads();

    // ---- weighted sum: warp w -> rows = w (mod 4), lane l -> d = 4l..4l+3 ----
    const float4* Xb4 = (const float4*)(X + (size_t)b * Sc * Dc) + l;
    float4 acc0 = make_float4(0.f, 0.f, 0.f, 0.f);
    float4 acc1 = make_float4(0.f, 0.f, 0.f, 0.f);
    int r = w;
    for (; r + 4 < len; r += 8) {
        const float aw0 = sh_attn[r], aw1 = sh_attn[r + 4];
        const float4 x0 = __ldg(&Xb4[(size_t)r * 32]);
        const float4 x1 = __ldg(&Xb4[(size_t)(r + 4) * 32]);
        acc0.x = fmaf(aw0, x0.x, acc0.x); acc0.y = fmaf(aw0, x0.y, acc0.y);
        acc0.z = fmaf(aw0, x0.z, acc0.z); acc0.w = fmaf(aw0, x0.w, acc0.w);
        acc1.x = fmaf(aw1, x1.x, acc1.x); acc1.y = fmaf(aw1, x1.y, acc1.y);
        acc1.z = fmaf(aw1, x1.z, acc1.z); acc1.w = fmaf(aw1, x1.w, acc1.w);
    }
    if (r < len) {
        const float aw = sh_attn[r];
        const float4 x0 = __ldg(&Xb4[(size_t)r * 32]);
        acc0.x = fmaf(aw, x0.x, acc0.x); acc0.y = fmaf(aw, x0.y, acc0.y);
        acc0.z = fmaf(aw, x0.z, acc0.z); acc0.w = fmaf(aw, x0.w, acc0.w);
    }
    acc0.x += acc1.x; acc0.y += acc1.y; acc0.z += acc1.z; acc0.w += acc1.w;
    *(float4*)&sh_ws[w * Dc + 4 * l] = acc0;
    __syncthreads();
    const float ao = sh_ws[tid] + sh_ws[Dc + tid] + sh_ws[2 * Dc + tid] + sh_ws[3 * Dc + tid];

    const float lastv = sh_attn[len - 1] * __ldg(&X[(size_t)b * Sc * Dc + (size_t)(len - 1) * Dc + tid]);
    const float outv = ao - lastv;
    sh_outv[tid] = outv;

    const float xi = __ldg(&Xitem[b * Dc + tid]);
    float r0 = lastv * lastv, r1 = outv * outv, r2 = lastv * outv, r3 = ao * xi;
#pragma unroll
    for (int o = 16; o; o >>= 1) {
        r0 += __shfl_xor_sync(0xffffffffu, r0, o);
        r1 += __shfl_xor_sync(0xffffffffu, r1, o);
        r2 += __shfl_xor_sync(0xffffffffu, r2, o);
        r3 += __shfl_xor_sync(0xffffffffu, r3, o);
    }
    if (l == 0) { sh_red[w] = r0; sh_red[4 + w] = r1; sh_red[8 + w] = r2; sh_red[12 + w] = r3; }
    __syncthreads();
    if (tid < 4)
        sh_res[tid] = sh_red[tid * 4] + sh_red[tid * 4 + 1] + sh_red[tid * 4 + 2] + sh_red[tid * 4 + 3];
    __syncthreads();

    const float normOut = sqrtf(fmaxf(sh_res[1], 1e-12f));

    out[b * (Dc + 1) + tid] = ao;
    if (tid == 0) {
        out[b * (Dc + 1) + Dc] = sh_res[3];
        const float cosp = sh_res[2] / (sqrtf(fmaxf(sh_res[0], 1e-12f)) * normOut);
        const float pl = (1.f - cosp) * 0.5f;
        g_posloss[b] = softplus_f(-pl);
    }

    const float o0 = sh_outv[4 * l], o1 = sh_outv[4 * l + 1];
    const float o2 = sh_outv[4 * l + 2], o3 = sh_outv[4 * l + 3];
    const float4* Ob = (const float4*)(origin + (size_t)b * Nc * Dc);
    float nloss = 0.f;
    for (int n = w; n < Nc; n += 4) {
        const float4 og = Ob[n * 32 + l];
        float dot = og.x * o0 + og.y * o1 + og.z * o2 + og.w * o3;
        float nn = og.x * og.x + og.y * og.y + og.z * og.z + og.w * og.w;
#pragma unroll
        for (int o = 16; o; o >>= 1) {
            dot += __shfl_xor_sync(0xffffffffu, dot, o);
            nn  += __shfl_xor_sync(0xffffffffu, nn, o);
        }
        const float cosn = dot / (sqrtf(fmaxf(nn, 1e-12f)) * normOut);
        nloss += softplus_f((1.f - cosn) * 0.5f);
    }
    __syncthreads();
    if (l == 0) sh_w[w] = nloss;
    __syncthreads();
    if (tid == 0) g_negsum[b] = sh_w[0] + sh_w[1] + sh_w[2] + sh_w[3];

    // ---- last-block aux finalization ----
    __threadfence();
    __syncthreads();
    if (tid == 0) sh_last = (atomicAdd(&g_done, 1) == Bc - 1);
    __syncthreads();
    if (sh_last) {
        __threadfence();
        float v = 0.f;
#pragma unroll
        for (int j = 0; j < 8; j++) v += g_posloss[tid + j * 128];
#pragma unroll
        for (int o = 16; o; o >>= 1) v += __shfl_xor_sync(0xffffffffu, v, o);
        if (l == 0) sh_w[w] = v;
        __syncthreads();
        const float tot = sh_w[0] + sh_w[1] + sh_w[2] + sh_w[3];
#pragma unroll
        for (int j = 0; j < 8; j++) {
            const int bb = tid + j * 128;
            out[OUT_CONCAT + bb] = tot + g_negsum[bb];
        }
        if (tid == 0) { g_done = 0; g_flags = 0; g_pdone = 0; }
    }
}

extern "C" void kernel_launch(void* const* d_in, const int* in_sizes, int n_in,
                              void* d_out, int out_size) {
    const float* X      = (const float*)d_in[0];
    const float* pos    = (const float*)d_in[1];
    const float* Xitem  = (const float*)d_in[2];
    const void*  mask   = d_in[3];
    const float* origin = (const float*)d_in[4];
    const float* Wp     = (const float*)d_in[5];
    const float* We     = (const float*)d_in[6];
    const float* z      = (const float*)d_in[7];
    float* out = (float*)d_out;

    cudaFuncSetAttribute(k1_mma, cudaFuncAttributeMaxDynamicSharedMemorySize, SMEM_K1);

    k1_mma<<<148, 256, SMEM_K1>>>(X, We, z, pos, Wp, (const uint4*)mask);
    k2_finalize<<<Bc, Dc>>>(X, mask, Xitem, origin, out);
}